// round 6
// baseline (speedup 1.0000x reference)
#include <cuda_runtime.h>
#include <math.h>
#include <stdint.h>

#define Bb  64
#define Tt  48
#define Hh  512
#define Ee  512
#define ATT 196
#define AF  2048
#define FCD 2048
#define Vv  10000

// ---------------- device scratch (no allocs allowed) ----------------
__device__ __align__(16) float g_h[Bb*Tt*Hh];
__device__ __align__(16) float g_c[Bb*Tt*Hh];
__device__ __align__(16) float g_fcp[8][Bb*Ee];
__device__ __align__(16) float g_patt[Bb*ATT*Ee];
__device__ __align__(16) float g_attmean[Bb*AF];
__device__ __align__(16) float g_Wq[Ee*1024];
__device__ __align__(16) float g_bq[Ee];
__device__ __align__(16) float g_catX[Bb*4096];
__device__ __align__(16) float g_catF1[Bb*1024];
__device__ __align__(16) float g_catF2[Bb*1024];
__device__ __align__(16) float g_hcat[Bb*1024];
__device__ __align__(16) float g_qp[4][Bb*Hh];
__device__ __align__(16) float g_q[Bb*Hh];
__device__ __align__(16) float g_attlog[Bb*ATT];
__device__ __align__(16) float g_gatesP[8][Bb*1024];
__device__ __align__(16) float g_cg0P[8][Bb*Hh];
__device__ __align__(16) float g_cg1P[8][Bb*Hh];
__device__ __align__(16) float g_f1P[4][Bb*Hh];
__device__ __align__(16) float g_f2P[4][Bb*Hh];
__device__ __align__(16) float g_ca[Bb*Hh];
__device__ __align__(16) float g_cf[Bb*Hh];

// ---------------- init kernels ----------------
__global__ void k_zero_hc() {
    int idx = blockIdx.x * blockDim.x + threadIdx.x;
    int n = Bb*Tt*Hh;
    for (int i = idx; i < n; i += gridDim.x * blockDim.x) { g_h[i] = 0.f; g_c[i] = 0.f; }
}

__global__ void k_build_wq(const float* __restrict__ W_ha, const float* __restrict__ b_ha,
                           const float* __restrict__ W_hf, const float* __restrict__ b_hf) {
    int n = blockIdx.x;               // 0..511
    for (int k = threadIdx.x; k < Hh; k += blockDim.x) {
        g_Wq[n*1024 + k]      = W_ha[n*Hh + k];
        g_Wq[n*1024 + Hh + k] = W_hf[n*Hh + k];
    }
    if (threadIdx.x == 0) g_bq[n] = b_ha[n] + b_hf[n];
}

__global__ void k_attmean(const float* __restrict__ att_feats) {
    int b = blockIdx.y;
    int d = blockIdx.x * blockDim.x + threadIdx.x;   // < AF
    const float* p = att_feats + (size_t)b*ATT*AF + d;
    float acc = 0.f;
    for (int a = 0; a < ATT; a++) acc += p[(size_t)a*AF];
    g_attmean[b*AF + d] = acc * (1.0f/ATT);
}

// ---------------- big GEMM: C[M,N] = A[M,K] @ W[N,K]^T + bias ----------------
// mode 0: A = Aext (att_feats flat), C = g_patt
// mode 1: A = g_h (flat [B*T, H]),   C = Cext (d_out)
__global__ void __launch_bounds__(256)
k_gemm_big(int mode, const float* __restrict__ Aext, const float* __restrict__ W,
           const float* __restrict__ bias, float* __restrict__ Cext,
           int M, int N, int K) {
    const float* A = (mode == 0) ? Aext : g_h;
    float*       C = (mode == 0) ? g_patt : Cext;

    __shared__ float As[8][128];
    __shared__ float Ws[8][128];
    int tid = threadIdx.x;
    int tx = tid & 15, ty = tid >> 4;
    int m0 = blockIdx.y * 128, n0 = blockIdx.x * 128;
    int lr = tid >> 1;
    int lk = (tid & 1) * 4;
    float acc[8][8];
#pragma unroll
    for (int i = 0; i < 8; i++)
#pragma unroll
        for (int j = 0; j < 8; j++) acc[i][j] = 0.f;

    for (int k0 = 0; k0 < K; k0 += 8) {
        {
            int gm = m0 + lr;
            float4 v = make_float4(0.f,0.f,0.f,0.f);
            if (gm < M) v = *(const float4*)&A[(size_t)gm*K + k0 + lk];
            As[lk+0][lr] = v.x; As[lk+1][lr] = v.y; As[lk+2][lr] = v.z; As[lk+3][lr] = v.w;
        }
        {
            int gn = n0 + lr;
            float4 v = make_float4(0.f,0.f,0.f,0.f);
            if (gn < N) v = *(const float4*)&W[(size_t)gn*K + k0 + lk];
            Ws[lk+0][lr] = v.x; Ws[lk+1][lr] = v.y; Ws[lk+2][lr] = v.z; Ws[lk+3][lr] = v.w;
        }
        __syncthreads();
#pragma unroll
        for (int k = 0; k < 8; k++) {
            float4 a0 = *(const float4*)&As[k][ty*4];
            float4 a1 = *(const float4*)&As[k][64 + ty*4];
            float4 w0 = *(const float4*)&Ws[k][tx*4];
            float4 w1 = *(const float4*)&Ws[k][64 + tx*4];
            float av[8] = {a0.x,a0.y,a0.z,a0.w,a1.x,a1.y,a1.z,a1.w};
            float wv[8] = {w0.x,w0.y,w0.z,w0.w,w1.x,w1.y,w1.z,w1.w};
#pragma unroll
            for (int i = 0; i < 8; i++)
#pragma unroll
                for (int j = 0; j < 8; j++) acc[i][j] += av[i]*wv[j];
        }
        __syncthreads();
    }
#pragma unroll
    for (int si = 0; si < 2; si++)
#pragma unroll
        for (int ii = 0; ii < 4; ii++) {
            int gm = m0 + si*64 + ty*4 + ii;
            if (gm >= M) continue;
#pragma unroll
            for (int sj = 0; sj < 2; sj++)
#pragma unroll
                for (int jj = 0; jj < 4; jj++) {
                    int gn = n0 + sj*64 + tx*4 + jj;
                    if (gn < N) C[(size_t)gm*N + gn] = acc[si*4+ii][sj*4+jj] + bias[gn];
                }
        }
}

// ---------------- small-M split-K multi-job GEMM (M=64, tile 64x64, Ks=256) ----
// partials: Cp[split][64][N], no bias (added by consumers)
__global__ void __launch_bounds__(256)
k_gemm_small(int mode, const float* __restrict__ fc_feats, const float* __restrict__ W_fc,
             const float* __restrict__ wH, const float* __restrict__ wI,
             const float* __restrict__ wf1, const float* __restrict__ wf2) {
    const float* A; int lda; const float* W; int ldw; float* Cp; int N, ntile; int local;
    int bx = blockIdx.x;
    if (mode == 0)      { A = fc_feats;    lda = FCD;  W = W_fc; ldw = FCD;  N = Ee;   ntile = 8;  Cp = &g_fcp[0][0];   local = bx; }
    else if (mode == 1) { A = g_hcat;      lda = 1024; W = g_Wq; ldw = 1024; N = Hh;   ntile = 8;  Cp = &g_qp[0][0];    local = bx; }
    else {
        if (bx < 128)      { A = g_catX;      lda = 4096; W = wH;      ldw = 2048; N = 1024; ntile = 16; Cp = &g_gatesP[0][0]; local = bx; }
        else if (bx < 192) { A = g_catX;      lda = 4096; W = wI;      ldw = 4096; N = 512;  ntile = 8;  Cp = &g_cg0P[0][0];   local = bx - 128; }
        else if (bx < 256) { A = g_catX+2048; lda = 4096; W = wI+2048; ldw = 4096; N = 512;  ntile = 8;  Cp = &g_cg1P[0][0];   local = bx - 192; }
        else if (bx < 288) { A = g_catF1;     lda = 1024; W = wf1;     ldw = 1024; N = 512;  ntile = 8;  Cp = &g_f1P[0][0];    local = bx - 256; }
        else               { A = g_catF2;     lda = 1024; W = wf2;     ldw = 1024; N = 512;  ntile = 8;  Cp = &g_f2P[0][0];    local = bx - 288; }
    }
    int tile = local % ntile, split = local / ntile;
    int n0 = tile * 64, k0 = split * 256;

    __shared__ float As[16][64];
    __shared__ float Ws[16][64];
    int tid = threadIdx.x;
    int tx = tid & 15, ty = tid >> 4;
    int lr = tid >> 2;             // 0..63
    int lk = (tid & 3) * 4;        // 0,4,8,12
    float acc[4][4];
#pragma unroll
    for (int i = 0; i < 4; i++)
#pragma unroll
        for (int j = 0; j < 4; j++) acc[i][j] = 0.f;

    for (int kk = 0; kk < 256; kk += 16) {
        {
            float4 v = *(const float4*)&A[(size_t)lr*lda + k0 + kk + lk];
            As[lk+0][lr] = v.x; As[lk+1][lr] = v.y; As[lk+2][lr] = v.z; As[lk+3][lr] = v.w;
        }
        {
            float4 v = *(const float4*)&W[(size_t)(n0+lr)*ldw + k0 + kk + lk];
            Ws[lk+0][lr] = v.x; Ws[lk+1][lr] = v.y; Ws[lk+2][lr] = v.z; Ws[lk+3][lr] = v.w;
        }
        __syncthreads();
#pragma unroll
        for (int k = 0; k < 16; k++) {
            float4 a = *(const float4*)&As[k][ty*4];
            float4 w = *(const float4*)&Ws[k][tx*4];
            float av[4] = {a.x,a.y,a.z,a.w};
            float wv[4] = {w.x,w.y,w.z,w.w};
#pragma unroll
            for (int i = 0; i < 4; i++)
#pragma unroll
                for (int j = 0; j < 4; j++) acc[i][j] += av[i]*wv[j];
        }
        __syncthreads();
    }
    float* Cb = Cp + (size_t)split * 64 * N;
#pragma unroll
    for (int i = 0; i < 4; i++) {
        int m = ty*4 + i;
#pragma unroll
        for (int j = 0; j < 4; j++) Cb[(size_t)m*N + n0 + tx*4 + j] = acc[i][j];
    }
}

// ---------------- per-step gather ----------------
__global__ void k_gather(int i, const int* __restrict__ word_idx, const int* __restrict__ father_idx,
                         const float* __restrict__ embed_tab, const float* __restrict__ b_fc) {
    int b = blockIdx.x;
    int father = father_idx[b*Tt + i];
    bool isFirst = (i == 0);
    int ip = isFirst ? 0 : i - 1;
    bool useF = (!isFirst) && (((i - 1) % 3) != 0);
    int wa = word_idx[b*Tt + father];
    int wf = word_idx[b*Tt + ip];
    for (int d = threadIdx.x; d < Hh; d += blockDim.x) {
        float xa, ha, ca;
        if (isFirst) {
            float s = b_fc[d];
#pragma unroll
            for (int p = 0; p < 8; p++) s += g_fcp[p][b*Ee + d];
            xa = s; ha = 0.f; ca = 0.f;
        } else {
            xa = embed_tab[(size_t)wa*Ee + d];
            ha = g_h[(b*Tt + father)*Hh + d];
            ca = g_c[(b*Tt + father)*Hh + d];
        }
        float xf = 0.f, hf = 0.f, cf = 0.f;
        if (useF) {
            xf = embed_tab[(size_t)wf*Ee + d];
            hf = g_h[(b*Tt + ip)*Hh + d];
            cf = g_c[(b*Tt + ip)*Hh + d];
        }
        g_catX[b*4096 + d]        = xa;
        g_catX[b*4096 + 512 + d]  = xf;
        g_catX[b*4096 + 1024 + d] = ha;
        g_catX[b*4096 + 1536 + d] = hf;
        g_catF1[b*1024 + d]       = xa;
        g_catF1[b*1024 + 512 + d] = ha;
        g_catF2[b*1024 + d]       = xf;
        g_catF2[b*1024 + 512 + d] = hf;
        g_hcat[b*1024 + d]        = ha;
        g_hcat[b*1024 + 512 + d]  = hf;
        g_ca[b*Hh + d] = ca;
        g_cf[b*Hh + d] = cf;
    }
    if (isFirst) {
        for (int d = threadIdx.x; d < AF; d += blockDim.x)
            g_catX[b*4096 + 2048 + d] = g_attmean[b*AF + d];
    }
}

__global__ void k_qfix() {
    int idx = blockIdx.x * blockDim.x + threadIdx.x;  // B*H
    if (idx < Bb*Hh) {
        float s = g_bq[idx & (Hh-1)];
#pragma unroll
        for (int p = 0; p < 4; p++) s += g_qp[p][idx];
        g_q[idx] = s;
    }
}

__global__ void k_attlogits(const float* __restrict__ W_alpha, const float* __restrict__ b_alpha) {
    int r = blockIdx.x;                 // B*ATT
    int b = r / ATT;
    const float* pa = g_patt + (size_t)r*Ee;
    const float* q  = g_q + b*Ee;
    float acc = 0.f;
    for (int e = threadIdx.x; e < Ee; e += blockDim.x)
        acc += W_alpha[e] * tanhf(q[e] + pa[e]);
    __shared__ float red[4];
#pragma unroll
    for (int o = 16; o > 0; o >>= 1) acc += __shfl_down_sync(0xffffffffu, acc, o);
    if ((threadIdx.x & 31) == 0) red[threadIdx.x >> 5] = acc;
    __syncthreads();
    if (threadIdx.x == 0)
        g_attlog[r] = red[0] + red[1] + red[2] + red[3] + b_alpha[0];
}

__global__ void k_softwsum(const float* __restrict__ att_feats) {
    int b = blockIdx.x;
    int tid = threadIdx.x;              // 256
    __shared__ float w[ATT];
    __shared__ float red[8];
    __shared__ float sval[2];
    float v = (tid < ATT) ? g_attlog[b*ATT + tid] : -1e30f;
    float m = v;
#pragma unroll
    for (int o = 16; o > 0; o >>= 1) m = fmaxf(m, __shfl_xor_sync(0xffffffffu, m, o));
    if ((tid & 31) == 0) red[tid >> 5] = m;
    __syncthreads();
    if (tid == 0) {
        float mm = red[0];
        for (int k = 1; k < 8; k++) mm = fmaxf(mm, red[k]);
        sval[0] = mm;
    }
    __syncthreads();
    float bm = sval[0];
    float e = (tid < ATT) ? expf(v - bm) : 0.f;
    float s = e;
#pragma unroll
    for (int o = 16; o > 0; o >>= 1) s += __shfl_xor_sync(0xffffffffu, s, o);
    __syncthreads();
    if ((tid & 31) == 0) red[tid >> 5] = s;
    __syncthreads();
    if (tid == 0) {
        float ss = 0.f;
        for (int k = 0; k < 8; k++) ss += red[k];
        sval[1] = ss;
    }
    __syncthreads();
    if (tid < ATT) w[tid] = e / sval[1];
    __syncthreads();
    const float* base = att_feats + (size_t)b*ATT*AF;
    for (int d = tid; d < AF; d += 256) {
        float acc = 0.f;
#pragma unroll 4
        for (int a = 0; a < ATT; a++) acc += w[a] * base[(size_t)a*AF + d];
        g_catX[b*4096 + 2048 + d] = acc;
    }
}

__global__ void k_cell(int i, const float* __restrict__ bias_H, const float* __restrict__ bias_I,
                       const float* __restrict__ bias_f1, const float* __restrict__ bias_f2) {
    int b = blockIdx.x;
    for (int d = threadIdx.x; d < Hh; d += blockDim.x) {
        float gi = bias_H[d], go = bias_H[Hh + d];
#pragma unroll
        for (int p = 0; p < 8; p++) { gi += g_gatesP[p][b*1024 + d]; go += g_gatesP[p][b*1024 + 512 + d]; }
        float cg = bias_I[d];
#pragma unroll
        for (int p = 0; p < 8; p++) cg += g_cg0P[p][b*Hh + d] + g_cg1P[p][b*Hh + d];
        float f1 = bias_f1[d], f2 = bias_f2[d];
#pragma unroll
        for (int p = 0; p < 4; p++) { f1 += g_f1P[p][b*Hh + d]; f2 += g_f2P[p][b*Hh + d]; }
        gi = 1.f/(1.f + expf(-gi));
        go = 1.f/(1.f + expf(-go));
        cg = tanhf(cg);
        f1 = 1.f/(1.f + expf(-f1));
        f2 = 1.f/(1.f + expf(-f2));
        float nc = f1*g_ca[b*Hh + d] + f2*g_cf[b*Hh + d] + gi*cg;
        float nh = go * tanhf(nc);
        g_h[(b*Tt + i)*Hh + d] = nh;
        g_c[(b*Tt + i)*Hh + d] = nc;
    }
}

__global__ void k_logsoftmax(float* __restrict__ out) {
    int r = blockIdx.x;                 // B*T rows
    float* row = out + (size_t)r*Vv;
    int tid = threadIdx.x;              // 256
    __shared__ float red[8];
    __shared__ float sval[2];
    float m = -1e30f;
    for (int j = tid; j < Vv; j += 256) m = fmaxf(m, row[j]);
#pragma unroll
    for (int o = 16; o > 0; o >>= 1) m = fmaxf(m, __shfl_xor_sync(0xffffffffu, m, o));
    if ((tid & 31) == 0) red[tid >> 5] = m;
    __syncthreads();
    if (tid == 0) {
        float mm = red[0];
        for (int k = 1; k < 8; k++) mm = fmaxf(mm, red[k]);
        sval[0] = mm;
    }
    __syncthreads();
    float bm = sval[0];
    float s = 0.f;
    for (int j = tid; j < Vv; j += 256) s += expf(row[j] - bm);
#pragma unroll
    for (int o = 16; o > 0; o >>= 1) s += __shfl_xor_sync(0xffffffffu, s, o);
    __syncthreads();
    if ((tid & 31) == 0) red[tid >> 5] = s;
    __syncthreads();
    if (tid == 0) {
        float ss = 0.f;
        for (int k = 0; k < 8; k++) ss += red[k];
        sval[1] = ss;
    }
    __syncthreads();
    float lse = bm + logf(sval[1]);
    for (int j = tid; j < Vv; j += 256) row[j] = row[j] - lse;
}

// ---------------- host ----------------
extern "C" void kernel_launch(void* const* d_in, const int* in_sizes, int n_in,
                              void* d_out, int out_size) {
    const int*   word_idx   = (const int*)d_in[0];
    const int*   father_idx = (const int*)d_in[1];
    const float* fc_feats   = (const float*)d_in[2];
    const float* att_feats  = (const float*)d_in[3];
    const float* W_fc       = (const float*)d_in[4];
    const float* b_fc       = (const float*)d_in[5];
    const float* W_att      = (const float*)d_in[6];
    const float* b_att      = (const float*)d_in[7];
    const float* embed_tab  = (const float*)d_in[8];
    const float* weight_f1  = (const float*)d_in[9];
    const float* bias_f1    = (const float*)d_in[10];
    const float* weight_f2  = (const float*)d_in[11];
    const float* bias_f2    = (const float*)d_in[12];
    const float* weight_H   = (const float*)d_in[13];
    const float* bias_H     = (const float*)d_in[14];
    const float* weight_I   = (const float*)d_in[15];
    const float* bias_I     = (const float*)d_in[16];
    const float* W_ha       = (const float*)d_in[17];
    const float* b_ha       = (const float*)d_in[18];
    const float* W_hf       = (const float*)d_in[19];
    const float* b_hf       = (const float*)d_in[20];
    const float* W_alpha    = (const float*)d_in[21];
    const float* b_alpha    = (const float*)d_in[22];
    const float* W_logit    = (const float*)d_in[23];
    const float* b_logit    = (const float*)d_in[24];
    float* out = (float*)d_out;

    // init
    k_zero_hc<<<512, 256>>>();
    k_build_wq<<<Ee, 256>>>(W_ha, b_ha, W_hf, b_hf);
    {
        dim3 g(AF/256, Bb);
        k_attmean<<<g, 256>>>(att_feats);
    }
    // fc_emb partials
    k_gemm_small<<<64, 256>>>(0, fc_feats, W_fc, weight_H, weight_I, weight_f1, weight_f2);
    // p_att = att_feats @ W_att^T + b_att
    {
        dim3 g(Ee/128, (Bb*ATT)/128);   // (4, 98)
        k_gemm_big<<<g, 256>>>(0, att_feats, W_att, b_att, nullptr, Bb*ATT, Ee, AF);
    }

    // sequential tree-LSTM steps
    for (int i = 0; i < Tt; i++) {
        k_gather<<<Bb, 256>>>(i, word_idx, father_idx, embed_tab, b_fc);
        if (i > 0) {
            k_gemm_small<<<32, 256>>>(1, fc_feats, W_fc, weight_H, weight_I, weight_f1, weight_f2);
            k_qfix<<<(Bb*Hh + 255)/256, 256>>>();
            k_attlogits<<<Bb*ATT, 128>>>(W_alpha, b_alpha);
            k_softwsum<<<Bb, 256>>>(att_feats);
        }
        k_gemm_small<<<320, 256>>>(2, fc_feats, W_fc, weight_H, weight_I, weight_f1, weight_f2);
        k_cell<<<Bb, 256>>>(i, bias_H, bias_I, bias_f1, bias_f2);
    }

    // logits = h_states_flat @ W_logit^T + b_logit -> out, then log_softmax in-place
    {
        dim3 g((Vv + 127)/128, (Bb*Tt)/128);  // (79, 24)
        k_gemm_big<<<g, 256>>>(1, nullptr, W_logit, b_logit, out, Bb*Tt, Vv, Hh);
    }
    k_logsoftmax<<<Bb*Tt, 256>>>(out);
}

// round 10
// speedup vs baseline: 2.6570x; 2.6570x over previous
#include <cuda_runtime.h>
#include <math.h>
#include <stdint.h>

#define Bb  64
#define Tt  48
#define Hh  512
#define Ee  512
#define ATT 196
#define AF  2048
#define FCD 2048
#define Vv  10000

// ---------------- device scratch (no allocs allowed) ----------------
__device__ __align__(16) float g_h[Bb*Tt*Hh];
__device__ __align__(16) float g_c[Bb*Tt*Hh];
__device__ __align__(16) float g_fcp[8][Bb*Ee];
__device__ __align__(16) float g_patt[Bb*ATT*Ee];     // att_feats @ W_att^T + b_att
__device__ __align__(16) float g_pI[Bb*ATT*Hh];       // att_feats @ WI_att^T
__device__ __align__(16) float g_Wq[Ee*1024];
__device__ __align__(16) float g_bq[Ee];
__device__ __align__(16) float g_catX[Bb*2048];       // [x1,x2,h1,h2]
__device__ __align__(16) float g_catF1[Bb*1024];
__device__ __align__(16) float g_catF2[Bb*1024];
__device__ __align__(16) float g_hcat[Bb*1024];
__device__ __align__(16) float g_qp[4][Bb*Hh];
__device__ __align__(16) float g_attlog[Bb*ATT];
__device__ __align__(16) float g_gatesP[8][Bb*1024];
__device__ __align__(16) float g_cg0P[8][Bb*Hh];
__device__ __align__(16) float g_cgatt[Bb*Hh];        // w @ P  (attention part of cellgate)
__device__ __align__(16) float g_f1P[4][Bb*Hh];
__device__ __align__(16) float g_f2P[4][Bb*Hh];
__device__ __align__(16) float g_ca[Bb*Hh];
__device__ __align__(16) float g_cf[Bb*Hh];

__device__ __forceinline__ float tanh_approx(float x) {
    float y;
    asm("tanh.approx.f32 %0, %1;" : "=f"(y) : "f"(x));
    return y;
}

// ---------------- init kernels ----------------
__global__ void k_zero_hc() {
    int idx = blockIdx.x * blockDim.x + threadIdx.x;
    int n = Bb*Tt*Hh;
    for (int i = idx; i < n; i += gridDim.x * blockDim.x) { g_h[i] = 0.f; g_c[i] = 0.f; }
}

__global__ void k_build_wq(const float* __restrict__ W_ha, const float* __restrict__ b_ha,
                           const float* __restrict__ W_hf, const float* __restrict__ b_hf) {
    int n = blockIdx.x;               // 0..511
    for (int k = threadIdx.x; k < Hh; k += blockDim.x) {
        g_Wq[n*1024 + k]      = W_ha[n*Hh + k];
        g_Wq[n*1024 + Hh + k] = W_hf[n*Hh + k];
    }
    if (threadIdx.x == 0) g_bq[n] = b_ha[n] + b_hf[n];
}

// mean over ATT of P rows -> g_cgatt (used by step 0: att_res = att_mean)
__global__ void k_pmean() {
    int b = blockIdx.x;
    int d = blockIdx.y * 128 + threadIdx.x;
    const float* p = g_pI + ((size_t)b*ATT)*Hh + d;
    float acc = 0.f;
#pragma unroll 4
    for (int a = 0; a < ATT; a++) acc += p[(size_t)a*Hh];
    g_cgatt[b*Hh + d] = acc * (1.0f/ATT);
}

// ---------------- big GEMM: C[M,N] = A[M,K] @ W[N,K(ldw)]^T (+ bias) ----------------
// Double-buffered smem pipeline, 128x128 tile, 8x8 acc. M mult of 128, K mult of 8.
// mode 0: A=Aext, C=g_patt; mode 2: A=Aext, C=g_pI; mode 1: A=g_h, C=Cext
__global__ void __launch_bounds__(256)
k_gemm_big(int mode, const float* __restrict__ Aext, const float* __restrict__ W, int ldw,
           const float* __restrict__ bias, float* __restrict__ Cext,
           int M, int N, int K) {
    const float* A = (mode == 1) ? g_h : Aext;
    float*       C = (mode == 0) ? g_patt : ((mode == 2) ? g_pI : Cext);

    __shared__ float As[2][8][132];
    __shared__ float Ws[2][8][132];
    int tid = threadIdx.x;
    int tx = tid & 15, ty = tid >> 4;
    int m0 = blockIdx.y * 128, n0 = blockIdx.x * 128;
    int lr = tid >> 1;                // 0..127
    int lk = (tid & 1) * 4;           // 0 or 4
    const float* Arow = A + (size_t)(m0 + lr)*K + lk;
    bool wok = (n0 + lr) < N;
    const float* Wrow = W + (size_t)(wok ? (n0 + lr) : 0)*ldw + lk;

    float acc[8][8];
#pragma unroll
    for (int i = 0; i < 8; i++)
#pragma unroll
        for (int j = 0; j < 8; j++) acc[i][j] = 0.f;

    float4 va = *(const float4*)&Arow[0];
    float4 vw = wok ? *(const float4*)&Wrow[0] : make_float4(0.f,0.f,0.f,0.f);
    As[0][lk+0][lr] = va.x; As[0][lk+1][lr] = va.y; As[0][lk+2][lr] = va.z; As[0][lk+3][lr] = va.w;
    Ws[0][lk+0][lr] = vw.x; Ws[0][lk+1][lr] = vw.y; Ws[0][lk+2][lr] = vw.z; Ws[0][lk+3][lr] = vw.w;
    __syncthreads();

    int buf = 0;
    for (int k0 = 0; k0 < K; k0 += 8) {
        bool more = (k0 + 8) < K;
        if (more) {
            va = *(const float4*)&Arow[k0 + 8];
            vw = wok ? *(const float4*)&Wrow[k0 + 8] : make_float4(0.f,0.f,0.f,0.f);
        }
#pragma unroll
        for (int k = 0; k < 8; k++) {
            float4 a0 = *(const float4*)&As[buf][k][ty*4];
            float4 a1 = *(const float4*)&As[buf][k][64 + ty*4];
            float4 w0 = *(const float4*)&Ws[buf][k][tx*4];
            float4 w1 = *(const float4*)&Ws[buf][k][64 + tx*4];
            float av[8] = {a0.x,a0.y,a0.z,a0.w,a1.x,a1.y,a1.z,a1.w};
            float wv[8] = {w0.x,w0.y,w0.z,w0.w,w1.x,w1.y,w1.z,w1.w};
#pragma unroll
            for (int i = 0; i < 8; i++)
#pragma unroll
                for (int j = 0; j < 8; j++) acc[i][j] += av[i]*wv[j];
        }
        if (more) {
            int nb = buf ^ 1;
            As[nb][lk+0][lr] = va.x; As[nb][lk+1][lr] = va.y; As[nb][lk+2][lr] = va.z; As[nb][lk+3][lr] = va.w;
            Ws[nb][lk+0][lr] = vw.x; Ws[nb][lk+1][lr] = vw.y; Ws[nb][lk+2][lr] = vw.z; Ws[nb][lk+3][lr] = vw.w;
        }
        __syncthreads();
        buf ^= 1;
    }

#pragma unroll
    for (int si = 0; si < 2; si++)
#pragma unroll
        for (int ii = 0; ii < 4; ii++) {
            int gm = m0 + si*64 + ty*4 + ii;
#pragma unroll
            for (int sj = 0; sj < 2; sj++)
#pragma unroll
                for (int jj = 0; jj < 4; jj++) {
                    int gn = n0 + sj*64 + tx*4 + jj;
                    if (gn < N) {
                        float bv = bias ? bias[gn] : 0.f;
                        C[(size_t)gm*N + gn] = acc[si*4+ii][sj*4+jj] + bv;
                    }
                }
        }
}

// ---------------- small-M multi-job GEMM: M=64, tile 64x128, K-slice 256 ----
// acc 4x8 per thread. partials Cp[split][64][N].
// mode 0: fc_emb partials (32 blocks)
// mode 2: per-step combined gates/cg0/f1/f2/q (144 blocks)
__global__ void __launch_bounds__(256)
k_gemm_small2(int mode, const float* __restrict__ fc_feats, const float* __restrict__ W_fc,
              const float* __restrict__ wH, const float* __restrict__ wI,
              const float* __restrict__ wf1, const float* __restrict__ wf2) {
    const float* A; int lda; const float* W; int ldw; float* Cp; int N, ntile; int local;
    int bx = blockIdx.x;
    if (mode == 0)      { A = fc_feats; lda = FCD;  W = W_fc; ldw = FCD;  N = Ee;   ntile = 4; Cp = &g_fcp[0][0];   local = bx; }
    else {
        if (bx < 64)       { A = g_catX;  lda = 2048; W = wH;   ldw = 2048; N = 1024; ntile = 8; Cp = &g_gatesP[0][0]; local = bx; }
        else if (bx < 96)  { A = g_catX;  lda = 2048; W = wI;   ldw = 4096; N = 512;  ntile = 4; Cp = &g_cg0P[0][0];   local = bx - 64; }
        else if (bx < 112) { A = g_catF1; lda = 1024; W = wf1;  ldw = 1024; N = 512;  ntile = 4; Cp = &g_f1P[0][0];    local = bx - 96; }
        else if (bx < 128) { A = g_catF2; lda = 1024; W = wf2;  ldw = 1024; N = 512;  ntile = 4; Cp = &g_f2P[0][0];    local = bx - 112; }
        else               { A = g_hcat;  lda = 1024; W = g_Wq; ldw = 1024; N = 512;  ntile = 4; Cp = &g_qp[0][0];     local = bx - 128; }
    }
    int tile = local % ntile, split = local / ntile;
    int n0 = tile * 128, k0 = split * 256;

    __shared__ float As[16][64];
    __shared__ float Ws[16][132];
    int tid = threadIdx.x;
    int tx = tid & 15, ty = tid >> 4;
    int ar = tid >> 2;             // 0..63
    int ak = (tid & 3) * 4;        // 0,4,8,12
    int wr = tid >> 1;             // 0..127
    int wk = (tid & 1) * 8;        // 0 or 8
    const float* Ap = A + (size_t)ar*lda + k0 + ak;
    const float* Wp = W + (size_t)(n0 + wr)*ldw + k0 + wk;

    float acc[4][8];
#pragma unroll
    for (int i = 0; i < 4; i++)
#pragma unroll
        for (int j = 0; j < 8; j++) acc[i][j] = 0.f;

    for (int kk = 0; kk < 256; kk += 16) {
        {
            float4 v = *(const float4*)&Ap[kk];
            As[ak+0][ar] = v.x; As[ak+1][ar] = v.y; As[ak+2][ar] = v.z; As[ak+3][ar] = v.w;
        }
        {
            float4 w0 = *(const float4*)&Wp[kk];
            float4 w1 = *(const float4*)&Wp[kk + 4];
            Ws[wk+0][wr] = w0.x; Ws[wk+1][wr] = w0.y; Ws[wk+2][wr] = w0.z; Ws[wk+3][wr] = w0.w;
            Ws[wk+4][wr] = w1.x; Ws[wk+5][wr] = w1.y; Ws[wk+6][wr] = w1.z; Ws[wk+7][wr] = w1.w;
        }
        __syncthreads();
#pragma unroll
        for (int k = 0; k < 16; k++) {
            float4 a  = *(const float4*)&As[k][ty*4];
            float4 w0 = *(const float4*)&Ws[k][tx*8];
            float4 w1 = *(const float4*)&Ws[k][tx*8 + 4];
            float av[4] = {a.x,a.y,a.z,a.w};
            float wv[8] = {w0.x,w0.y,w0.z,w0.w,w1.x,w1.y,w1.z,w1.w};
#pragma unroll
            for (int i = 0; i < 4; i++)
#pragma unroll
                for (int j = 0; j < 8; j++) acc[i][j] += av[i]*wv[j];
        }
        __syncthreads();
    }
    float* Cb = Cp + (size_t)split * 64 * N;
#pragma unroll
    for (int i = 0; i < 4; i++) {
        int m = ty*4 + i;
        float4 o0 = make_float4(acc[i][0], acc[i][1], acc[i][2], acc[i][3]);
        float4 o1 = make_float4(acc[i][4], acc[i][5], acc[i][6], acc[i][7]);
        *(float4*)&Cb[(size_t)m*N + n0 + tx*8]     = o0;
        *(float4*)&Cb[(size_t)m*N + n0 + tx*8 + 4] = o1;
    }
}

// ---------------- gather for step 0 only ----------------
__global__ void k_gather0(const int* __restrict__ word_idx, const int* __restrict__ father_idx,
                          const float* __restrict__ b_fc) {
    int b = blockIdx.x;
    for (int d = threadIdx.x; d < Hh; d += blockDim.x) {
        float s = b_fc[d];
#pragma unroll
        for (int p = 0; p < 8; p++) s += g_fcp[p][b*Ee + d];
        float xa = s;
        g_catX[b*2048 + d]        = xa;
        g_catX[b*2048 + 512 + d]  = 0.f;
        g_catX[b*2048 + 1024 + d] = 0.f;
        g_catX[b*2048 + 1536 + d] = 0.f;
        g_catF1[b*1024 + d]       = xa;
        g_catF1[b*1024 + 512 + d] = 0.f;
        g_catF2[b*1024 + d]       = 0.f;
        g_catF2[b*1024 + 512 + d] = 0.f;
        g_hcat[b*1024 + d]        = 0.f;
        g_hcat[b*1024 + 512 + d]  = 0.f;
        g_ca[b*Hh + d] = 0.f;
        g_cf[b*Hh + d] = 0.f;
    }
}

// attention logits, fused q-partial reduction. grid (Bb, 7), 256 threads.
// b_alpha omitted: constant shift cancels in softmax.
__global__ void k_attlogits(const float* __restrict__ W_alpha) {
    int b = blockIdx.x;
    int c = blockIdx.y;        // 0..6, each handles 28 a's
    __shared__ float q[Ee];
    __shared__ float wa_s[Ee];
    int tid = threadIdx.x;
    for (int e = tid; e < Ee; e += 256) {
        float s = g_bq[e];
#pragma unroll
        for (int p = 0; p < 4; p++) s += g_qp[p][b*Ee + e];
        q[e] = s;
        wa_s[e] = W_alpha[e];
    }
    __syncthreads();
    int wid = tid >> 5, lane = tid & 31;
    for (int al = wid; al < 28; al += 8) {
        int a = c*28 + al;
        const float* pa = g_patt + ((size_t)(b*ATT) + a)*Ee;
        float acc = 0.f;
#pragma unroll
        for (int k = 0; k < 16; k++) {
            int e = lane + 32*k;
            acc += wa_s[e] * tanh_approx(q[e] + pa[e]);
        }
#pragma unroll
        for (int o = 16; o > 0; o >>= 1) acc += __shfl_down_sync(0xffffffffu, acc, o);
        if (lane == 0) g_attlog[b*ATT + a] = acc;
    }
}

// fused softmax + (w @ P) -> g_cgatt. grid (2, Bb), 128 threads, 2 cols/thread.
__global__ void k_wsum() {
    int b = blockIdx.y;
    int tid = threadIdx.x;              // 128
    __shared__ float w[ATT];
    __shared__ float red[4];
    __shared__ float sv;
    int wid = tid >> 5, lane = tid & 31;

    float v0 = g_attlog[b*ATT + tid];
    float v1 = (tid + 128 < ATT) ? g_attlog[b*ATT + tid + 128] : -1e30f;
    float m = fmaxf(v0, v1);
#pragma unroll
    for (int o = 16; o > 0; o >>= 1) m = fmaxf(m, __shfl_xor_sync(0xffffffffu, m, o));
    if (lane == 0) red[wid] = m;
    __syncthreads();
    if (tid == 0) sv = fmaxf(fmaxf(red[0], red[1]), fmaxf(red[2], red[3]));
    __syncthreads();
    float bm = sv;
    float e0 = __expf(v0 - bm);
    float e1 = (tid + 128 < ATT) ? __expf(v1 - bm) : 0.f;
    float s = e0 + e1;
#pragma unroll
    for (int o = 16; o > 0; o >>= 1) s += __shfl_xor_sync(0xffffffffu, s, o);
    __syncthreads();
    if (lane == 0) red[wid] = s;
    __syncthreads();
    if (tid == 0) sv = red[0] + red[1] + red[2] + red[3];
    __syncthreads();
    float inv = 1.0f / sv;
    w[tid] = e0 * inv;
    if (tid + 128 < ATT) w[tid + 128] = e1 * inv;
    __syncthreads();

    // cg_att[b, d0:d0+2] = sum_a w[a] * P[b, a, d0:d0+2]
    int d0 = blockIdx.x * 256 + tid * 2;
    const float* base = g_pI + (size_t)b*ATT*Hh + d0;
    float ax = 0.f, ay = 0.f;
#pragma unroll 4
    for (int a = 0; a < ATT; a++) {
        float2 v = *(const float2*)&base[(size_t)a*Hh];
        float ww = w[a];
        ax += ww * v.x; ay += ww * v.y;
    }
    *(float2*)&g_cgatt[b*Hh + d0] = make_float2(ax, ay);
}

// fused: cell for step i, then gather for step i+1 (same batch => in-block dep only)
__global__ void k_cellgather(int i, const int* __restrict__ word_idx, const int* __restrict__ father_idx,
                             const float* __restrict__ embed_tab,
                             const float* __restrict__ bias_H, const float* __restrict__ bias_I,
                             const float* __restrict__ bias_f1, const float* __restrict__ bias_f2) {
    int b = blockIdx.x;
    for (int d = threadIdx.x; d < Hh; d += blockDim.x) {
        float gi = bias_H[d], go = bias_H[Hh + d];
#pragma unroll
        for (int p = 0; p < 8; p++) { gi += g_gatesP[p][b*1024 + d]; go += g_gatesP[p][b*1024 + 512 + d]; }
        float cg = bias_I[d] + g_cgatt[b*Hh + d];
#pragma unroll
        for (int p = 0; p < 8; p++) cg += g_cg0P[p][b*Hh + d];
        float f1 = bias_f1[d], f2 = bias_f2[d];
#pragma unroll
        for (int p = 0; p < 4; p++) { f1 += g_f1P[p][b*Hh + d]; f2 += g_f2P[p][b*Hh + d]; }
        gi = 1.f/(1.f + expf(-gi));
        go = 1.f/(1.f + expf(-go));
        cg = tanhf(cg);
        f1 = 1.f/(1.f + expf(-f1));
        f2 = 1.f/(1.f + expf(-f2));
        float nc = f1*g_ca[b*Hh + d] + f2*g_cf[b*Hh + d] + gi*cg;
        float nh = go * tanhf(nc);
        g_h[(b*Tt + i)*Hh + d] = nh;
        g_c[(b*Tt + i)*Hh + d] = nc;
    }
    __syncthreads();   // global writes above are visible block-wide after this

    int ni = i + 1;
    if (ni >= Tt) return;
    int father = father_idx[b*Tt + ni];
    bool useF = (((ni - 1) % 3) != 0);
    int wa = word_idx[b*Tt + father];
    int wf = word_idx[b*Tt + ni - 1];
    for (int d = threadIdx.x; d < Hh; d += blockDim.x) {
        float xa = embed_tab[(size_t)wa*Ee + d];
        float ha = g_h[(b*Tt + father)*Hh + d];
        float ca = g_c[(b*Tt + father)*Hh + d];
        float xf = 0.f, hf = 0.f, cf = 0.f;
        if (useF) {
            xf = embed_tab[(size_t)wf*Ee + d];
            hf = g_h[(b*Tt + ni - 1)*Hh + d];
            cf = g_c[(b*Tt + ni - 1)*Hh + d];
        }
        g_catX[b*2048 + d]        = xa;
        g_catX[b*2048 + 512 + d]  = xf;
        g_catX[b*2048 + 1024 + d] = ha;
        g_catX[b*2048 + 1536 + d] = hf;
        g_catF1[b*1024 + d]       = xa;
        g_catF1[b*1024 + 512 + d] = ha;
        g_catF2[b*1024 + d]       = xf;
        g_catF2[b*1024 + 512 + d] = hf;
        g_hcat[b*1024 + d]        = ha;
        g_hcat[b*1024 + 512 + d]  = hf;
        g_ca[b*Hh + d] = ca;
        g_cf[b*Hh + d] = cf;
    }
}

// 1-pass online log-softmax over V=10000
__global__ void k_logsoftmax(float* __restrict__ out) {
    int r = blockIdx.x;                 // B*T rows
    float* row = out + (size_t)r*Vv;
    int tid = threadIdx.x;              // 256
    int wid = tid >> 5, lane = tid & 31;
    __shared__ float rm[8], rs[8];
    __shared__ float svM, svS;

    float m = -1e30f, s = 0.f;
    for (int j = tid; j < Vv; j += 256) {
        float v = row[j];
        if (v > m) { s = s*__expf(m - v) + 1.f; m = v; }
        else s += __expf(v - m);
    }
#pragma unroll
    for (int o = 16; o > 0; o >>= 1) {
        float mo = __shfl_xor_sync(0xffffffffu, m, o);
        float so = __shfl_xor_sync(0xffffffffu, s, o);
        float M = fmaxf(m, mo);
        s = s*__expf(m - M) + so*__expf(mo - M);
        m = M;
    }
    if (lane == 0) { rm[wid] = m; rs[wid] = s; }
    __syncthreads();
    if (tid == 0) {
        float M = rm[0], S = rs[0];
        for (int k = 1; k < 8; k++) {
            float M2 = fmaxf(M, rm[k]);
            S = S*__expf(M - M2) + rs[k]*__expf(rm[k] - M2);
            M = M2;
        }
        svM = M; svS = S;
    }
    __syncthreads();
    float lse = svM + logf(svS);
    for (int j = tid; j < Vv; j += 256) row[j] -= lse;
}

// ---------------- host ----------------
extern "C" void kernel_launch(void* const* d_in, const int* in_sizes, int n_in,
                              void* d_out, int out_size) {
    const int*   word_idx   = (const int*)d_in[0];
    const int*   father_idx = (const int*)d_in[1];
    const float* fc_feats   = (const float*)d_in[2];
    const float* att_feats  = (const float*)d_in[3];
    const float* W_fc       = (const float*)d_in[4];
    const float* b_fc       = (const float*)d_in[5];
    const float* W_att      = (const float*)d_in[6];
    const float* b_att      = (const float*)d_in[7];
    const float* embed_tab  = (const float*)d_in[8];
    const float* weight_f1  = (const float*)d_in[9];
    const float* bias_f1    = (const float*)d_in[10];
    const float* weight_f2  = (const float*)d_in[11];
    const float* bias_f2    = (const float*)d_in[12];
    const float* weight_H   = (const float*)d_in[13];
    const float* bias_H     = (const float*)d_in[14];
    const float* weight_I   = (const float*)d_in[15];
    const float* bias_I     = (const float*)d_in[16];
    const float* W_ha       = (const float*)d_in[17];
    const float* b_ha       = (const float*)d_in[18];
    const float* W_hf       = (const float*)d_in[19];
    const float* b_hf       = (const float*)d_in[20];
    const float* W_alpha    = (const float*)d_in[21];
    const float* b_alpha    = (const float*)d_in[22];
    const float* W_logit    = (const float*)d_in[23];
    const float* b_logit    = (const float*)d_in[24];
    float* out = (float*)d_out;
    (void)b_alpha; (void)n_in; (void)in_sizes; (void)out_size;

    // ---- one-time preprocessing (all on the capture stream; no stream/event objects) ----
    k_zero_hc<<<512, 256>>>();
    k_build_wq<<<Ee, 256>>>(W_ha, b_ha, W_hf, b_hf);
    // fc_emb partials
    k_gemm_small2<<<32, 256>>>(0, fc_feats, W_fc, weight_H, weight_I, weight_f1, weight_f2);
    // p_att = att_feats @ W_att^T + b_att
    {
        dim3 g(Ee/128, (Bb*ATT)/128);   // (4, 98)
        k_gemm_big<<<g, 256>>>(0, att_feats, W_att, AF, b_att, nullptr, Bb*ATT, Ee, AF);
    }
    // P = att_feats @ WI_att^T   (WI_att = weight_I columns [2048:4096])
    {
        dim3 g(Hh/128, (Bb*ATT)/128);   // (4, 98)
        k_gemm_big<<<g, 256>>>(2, att_feats, weight_I + 2048, 4096, nullptr, nullptr, Bb*ATT, Hh, AF);
    }
    // step-0 attention part: mean over P rows
    {
        dim3 g(Bb, 4);
        k_pmean<<<g, 128>>>();
    }
    k_gather0<<<Bb, 256>>>(word_idx, father_idx, b_fc);

    // ---- sequential tree-LSTM steps ----
    for (int i = 0; i < Tt; i++) {
        // combined gates/cg0/f1/f2/q GEMM
        k_gemm_small2<<<144, 256>>>(2, fc_feats, W_fc, weight_H, weight_I, weight_f1, weight_f2);
        if (i > 0) {
            dim3 ga(Bb, 7);
            k_attlogits<<<ga, 256>>>(W_alpha);
            dim3 gw(2, Bb);
            k_wsum<<<gw, 128>>>();
        }
        // cell(i) + gather(i+1)
        k_cellgather<<<Bb, 256>>>(i, word_idx, father_idx, embed_tab,
                                  bias_H, bias_I, bias_f1, bias_f2);
    }

    // logits = h_flat @ W_logit^T + b_logit -> out, then log_softmax in-place
    {
        dim3 g((Vv + 127)/128, (Bb*Tt)/128);  // (79, 24)
        k_gemm_big<<<g, 256>>>(1, nullptr, W_logit, Hh, b_logit, out, Bb*Tt, Vv, Hh);
    }
    k_logsoftmax<<<Bb*Tt, 256>>>(out);
}

// round 14
// speedup vs baseline: 2.9940x; 1.1268x over previous
#include <cuda_runtime.h>
#include <math.h>
#include <stdint.h>

#define Bb  64
#define Tt  48
#define Hh  512
#define Ee  512
#define ATT 196
#define AF  2048
#define FCD 2048
#define Vv  10000

// ---------------- device scratch (no allocs allowed) ----------------
__device__ __align__(16) float g_h[Bb*Tt*Hh];
__device__ __align__(16) float g_c[Bb*Tt*Hh];
__device__ __align__(16) float g_fcp[8][Bb*Ee];
__device__ __align__(16) float g_patt[Bb*ATT*Ee];     // att_feats @ W_att^T + b_att
__device__ __align__(16) float g_pI[Bb*ATT*Hh];       // att_feats @ WI_att^T
__device__ __align__(16) float g_Wq[Ee*1024];
__device__ __align__(16) float g_bq[Ee];
__device__ __align__(16) float g_catX[Bb*2048];       // [x1,x2,h1,h2]
__device__ __align__(16) float g_catF1[Bb*1024];
__device__ __align__(16) float g_catF2[Bb*1024];
__device__ __align__(16) float g_hcat[Bb*1024];
__device__ __align__(16) float g_qp[8][Bb*Hh];
__device__ __align__(16) float g_attlog[Bb*ATT];
__device__ __align__(16) float g_gatesP[16][Bb*1024];
__device__ __align__(16) float g_cg0P[16][Bb*Hh];
__device__ __align__(16) float g_cgatt[Bb*Hh];        // step-0 att_mean projected
__device__ __align__(16) float g_f1P[8][Bb*Hh];
__device__ __align__(16) float g_f2P[8][Bb*Hh];
__device__ __align__(16) float g_ca[Bb*Hh];
__device__ __align__(16) float g_cf[Bb*Hh];

__device__ __forceinline__ float tanh_approx(float x) {
    float y;
    asm("tanh.approx.f32 %0, %1;" : "=f"(y) : "f"(x));
    return y;
}

__device__ __forceinline__ unsigned f2tf32(float x) {
    unsigned u;
    asm("cvt.rna.tf32.f32 %0, %1;" : "=r"(u) : "f"(x));
    return u;
}

__device__ __forceinline__ void mma_tf32(float& d0, float& d1, float& d2, float& d3,
                                         unsigned a0, unsigned a1, unsigned a2, unsigned a3,
                                         unsigned b0, unsigned b1) {
    asm volatile("mma.sync.aligned.m16n8k8.row.col.f32.tf32.tf32.f32 "
        "{%0,%1,%2,%3}, {%4,%5,%6,%7}, {%8,%9}, {%0,%1,%2,%3};"
        : "+f"(d0), "+f"(d1), "+f"(d2), "+f"(d3)
        : "r"(a0), "r"(a1), "r"(a2), "r"(a3), "r"(b0), "r"(b1));
}

// ---------------- init kernels ----------------
__global__ void k_zero_hc() {
    int idx = blockIdx.x * blockDim.x + threadIdx.x;
    int n = Bb*Tt*Hh;
    for (int i = idx; i < n; i += gridDim.x * blockDim.x) { g_h[i] = 0.f; g_c[i] = 0.f; }
}

__global__ void k_build_wq(const float* __restrict__ W_ha, const float* __restrict__ b_ha,
                           const float* __restrict__ W_hf, const float* __restrict__ b_hf) {
    int n = blockIdx.x;               // 0..511
    for (int k = threadIdx.x; k < Hh; k += blockDim.x) {
        g_Wq[n*1024 + k]      = W_ha[n*Hh + k];
        g_Wq[n*1024 + Hh + k] = W_hf[n*Hh + k];
    }
    if (threadIdx.x == 0) g_bq[n] = b_ha[n] + b_hf[n];
}

// mean over ATT of P rows -> g_cgatt (used by step 0: att_res = att_mean)
__global__ void k_pmean() {
    int b = blockIdx.x;
    int d = blockIdx.y * 128 + threadIdx.x;
    const float* p = g_pI + ((size_t)b*ATT)*Hh + d;
    float acc = 0.f;
#pragma unroll 4
    for (int a = 0; a < ATT; a++) acc += p[(size_t)a*Hh];
    g_cgatt[b*Hh + d] = acc * (1.0f/ATT);
}

// ---------------- big GEMM (3xTF32 tensor core) ----------------
// C[M,N] = A[M,K] @ W[N,K(ldw)]^T (+ bias). Block 256thr, tile 128x128, Ktile 16.
// M % 128 == 0, K % 16 == 0. N guarded.
// mode 0: A=Aext, C=g_patt; mode 2: A=Aext, C=g_pI; mode 1: A=g_h, C=Cext
__global__ void __launch_bounds__(256)
k_gemm_big(int mode, const float* __restrict__ Aext, const float* __restrict__ W, int ldw,
           const float* __restrict__ bias, float* __restrict__ Cext,
           int M, int N, int K) {
    const float* A = (mode == 1) ? g_h : Aext;
    float*       C = (mode == 0) ? g_patt : ((mode == 2) ? g_pI : Cext);

    __shared__ float As[128][20];   // [m][k], pad 20 -> conflict-free frag loads
    __shared__ float Ws[128][20];   // [n][k]

    int tid = threadIdx.x;
    int m0 = blockIdx.y * 128, n0 = blockIdx.x * 128;
    int warp = tid >> 5, lane = tid & 31;
    int grp = lane >> 2, qd = lane & 3;
    int wm = (warp & 1) * 64;       // warp tile 64(m) x 32(n)
    int wn = (warp >> 1) * 32;

    // staging indices: 256 threads load 128 rows x 16 k
    int ar = tid >> 1;              // 0..127
    int ak = (tid & 1) * 8;         // 0 or 8
    const float* Arow = A + (size_t)(m0 + ar)*K;
    bool wok = (n0 + ar) < N;
    const float* Wrow = W + (size_t)(wok ? (n0 + ar) : 0)*ldw;

    float acc[4][4][4];
#pragma unroll
    for (int mi = 0; mi < 4; mi++)
#pragma unroll
        for (int ni = 0; ni < 4; ni++)
#pragma unroll
            for (int r = 0; r < 4; r++) acc[mi][ni][r] = 0.f;

    for (int k0 = 0; k0 < K; k0 += 16) {
        float4 va0 = *(const float4*)&Arow[k0 + ak];
        float4 va1 = *(const float4*)&Arow[k0 + ak + 4];
        float4 vw0 = wok ? *(const float4*)&Wrow[k0 + ak]     : make_float4(0.f,0.f,0.f,0.f);
        float4 vw1 = wok ? *(const float4*)&Wrow[k0 + ak + 4] : make_float4(0.f,0.f,0.f,0.f);
        __syncthreads();
        *(float4*)&As[ar][ak]     = va0;
        *(float4*)&As[ar][ak + 4] = va1;
        *(float4*)&Ws[ar][ak]     = vw0;
        *(float4*)&Ws[ar][ak + 4] = vw1;
        __syncthreads();

#pragma unroll
        for (int ks = 0; ks < 16; ks += 8) {
            // A fragments (hi/lo) for 4 m16 tiles
            unsigned ahi[4][4], alo[4][4];
#pragma unroll
            for (int mi = 0; mi < 4; mi++) {
                int r0 = wm + mi*16 + grp;
                float f0 = As[r0][ks + qd];
                float f1 = As[r0 + 8][ks + qd];
                float f2 = As[r0][ks + qd + 4];
                float f3 = As[r0 + 8][ks + qd + 4];
                ahi[mi][0] = f2tf32(f0); alo[mi][0] = f2tf32(f0 - __uint_as_float(ahi[mi][0]));
                ahi[mi][1] = f2tf32(f1); alo[mi][1] = f2tf32(f1 - __uint_as_float(ahi[mi][1]));
                ahi[mi][2] = f2tf32(f2); alo[mi][2] = f2tf32(f2 - __uint_as_float(ahi[mi][2]));
                ahi[mi][3] = f2tf32(f3); alo[mi][3] = f2tf32(f3 - __uint_as_float(ahi[mi][3]));
            }
#pragma unroll
            for (int ni = 0; ni < 4; ni++) {
                int cn = wn + ni*8 + grp;
                float g0 = Ws[cn][ks + qd];
                float g1 = Ws[cn][ks + qd + 4];
                unsigned bh0 = f2tf32(g0), bh1 = f2tf32(g1);
                unsigned bl0 = f2tf32(g0 - __uint_as_float(bh0));
                unsigned bl1 = f2tf32(g1 - __uint_as_float(bh1));
#pragma unroll
                for (int mi = 0; mi < 4; mi++) {
                    float* d = acc[mi][ni];
                    mma_tf32(d[0],d[1],d[2],d[3], ahi[mi][0],ahi[mi][1],ahi[mi][2],ahi[mi][3], bl0,bl1);
                    mma_tf32(d[0],d[1],d[2],d[3], alo[mi][0],alo[mi][1],alo[mi][2],alo[mi][3], bh0,bh1);
                    mma_tf32(d[0],d[1],d[2],d[3], ahi[mi][0],ahi[mi][1],ahi[mi][2],ahi[mi][3], bh0,bh1);
                }
            }
        }
    }

    // epilogue: c0 (r, 2qd), c1 (r, 2qd+1), c2 (r+8, 2qd), c3 (r+8, 2qd+1)
#pragma unroll
    for (int mi = 0; mi < 4; mi++) {
#pragma unroll
        for (int ni = 0; ni < 4; ni++) {
            int r0 = m0 + wm + mi*16 + grp;
            int cb = n0 + wn + ni*8 + 2*qd;
            float* d = acc[mi][ni];
            float bv0 = 0.f, bv1 = 0.f;
            if (bias) {
                if (cb < N) bv0 = bias[cb];
                if (cb + 1 < N) bv1 = bias[cb + 1];
            }
            if (cb < N)     C[(size_t)r0*N + cb]           = d[0] + bv0;
            if (cb + 1 < N) C[(size_t)r0*N + cb + 1]       = d[1] + bv1;
            if (cb < N)     C[(size_t)(r0 + 8)*N + cb]     = d[2] + bv0;
            if (cb + 1 < N) C[(size_t)(r0 + 8)*N + cb + 1] = d[3] + bv1;
        }
    }
}

// ---------------- small-M multi-job GEMM: M=64, tile 64x128 ----
// mode 0: fc_emb partials (K-slice 256, 32 blocks)
// mode 2: per-step combined gates/cg0/f1/f2/q (K-slice 128, 288 blocks)
__global__ void __launch_bounds__(256)
k_gemm_small2(int mode, const float* __restrict__ fc_feats, const float* __restrict__ W_fc,
              const float* __restrict__ wH, const float* __restrict__ wI,
              const float* __restrict__ wf1, const float* __restrict__ wf2) {
    const float* A; int lda; const float* W; int ldw; float* Cp; int N, ntile; int local; int kspan;
    int bx = blockIdx.x;
    if (mode == 0)      { A = fc_feats; lda = FCD;  W = W_fc; ldw = FCD;  N = Ee;   ntile = 4; Cp = &g_fcp[0][0];   local = bx; kspan = 256; }
    else {
        kspan = 128;
        if (bx < 128)      { A = g_catX;  lda = 2048; W = wH;   ldw = 2048; N = 1024; ntile = 8; Cp = &g_gatesP[0][0]; local = bx; }
        else if (bx < 192) { A = g_catX;  lda = 2048; W = wI;   ldw = 4096; N = 512;  ntile = 4; Cp = &g_cg0P[0][0];   local = bx - 128; }
        else if (bx < 224) { A = g_catF1; lda = 1024; W = wf1;  ldw = 1024; N = 512;  ntile = 4; Cp = &g_f1P[0][0];    local = bx - 192; }
        else if (bx < 256) { A = g_catF2; lda = 1024; W = wf2;  ldw = 1024; N = 512;  ntile = 4; Cp = &g_f2P[0][0];    local = bx - 224; }
        else               { A = g_hcat;  lda = 1024; W = g_Wq; ldw = 1024; N = 512;  ntile = 4; Cp = &g_qp[0][0];     local = bx - 256; }
    }
    int tile = local % ntile, split = local / ntile;
    int n0 = tile * 128, k0 = split * kspan;

    __shared__ float As[16][64];
    __shared__ float Ws[16][132];
    int tid = threadIdx.x;
    int tx = tid & 15, ty = tid >> 4;
    int ar = tid >> 2;             // 0..63
    int ak = (tid & 3) * 4;        // 0,4,8,12
    int wr = tid >> 1;             // 0..127
    int wk = (tid & 1) * 8;        // 0 or 8
    const float* Ap = A + (size_t)ar*lda + k0 + ak;
    const float* Wp = W + (size_t)(n0 + wr)*ldw + k0 + wk;

    float acc[4][8];
#pragma unroll
    for (int i = 0; i < 4; i++)
#pragma unroll
        for (int j = 0; j < 8; j++) acc[i][j] = 0.f;

    for (int kk = 0; kk < kspan; kk += 16) {
        {
            float4 v = *(const float4*)&Ap[kk];
            As[ak+0][ar] = v.x; As[ak+1][ar] = v.y; As[ak+2][ar] = v.z; As[ak+3][ar] = v.w;
        }
        {
            float4 w0 = *(const float4*)&Wp[kk];
            float4 w1 = *(const float4*)&Wp[kk + 4];
            Ws[wk+0][wr] = w0.x; Ws[wk+1][wr] = w0.y; Ws[wk+2][wr] = w0.z; Ws[wk+3][wr] = w0.w;
            Ws[wk+4][wr] = w1.x; Ws[wk+5][wr] = w1.y; Ws[wk+6][wr] = w1.z; Ws[wk+7][wr] = w1.w;
        }
        __syncthreads();
#pragma unroll
        for (int k = 0; k < 16; k++) {
            float4 a  = *(const float4*)&As[k][ty*4];
            float4 w0 = *(const float4*)&Ws[k][tx*8];
            float4 w1 = *(const float4*)&Ws[k][tx*8 + 4];
            float av[4] = {a.x,a.y,a.z,a.w};
            float wv[8] = {w0.x,w0.y,w0.z,w0.w,w1.x,w1.y,w1.z,w1.w};
#pragma unroll
            for (int i = 0; i < 4; i++)
#pragma unroll
                for (int j = 0; j < 8; j++) acc[i][j] += av[i]*wv[j];
        }
        __syncthreads();
    }
    float* Cb = Cp + (size_t)split * 64 * N;
#pragma unroll
    for (int i = 0; i < 4; i++) {
        int m = ty*4 + i;
        float4 o0 = make_float4(acc[i][0], acc[i][1], acc[i][2], acc[i][3]);
        float4 o1 = make_float4(acc[i][4], acc[i][5], acc[i][6], acc[i][7]);
        *(float4*)&Cb[(size_t)m*N + n0 + tx*8]     = o0;
        *(float4*)&Cb[(size_t)m*N + n0 + tx*8 + 4] = o1;
    }
}

// ---------------- gather for step 0 only ----------------
__global__ void k_gather0(const float* __restrict__ b_fc) {
    int b = blockIdx.x;
    for (int d = threadIdx.x; d < Hh; d += blockDim.x) {
        float s = b_fc[d];
#pragma unroll
        for (int p = 0; p < 8; p++) s += g_fcp[p][b*Ee + d];
        float xa = s;
        g_catX[b*2048 + d]        = xa;
        g_catX[b*2048 + 512 + d]  = 0.f;
        g_catX[b*2048 + 1024 + d] = 0.f;
        g_catX[b*2048 + 1536 + d] = 0.f;
        g_catF1[b*1024 + d]       = xa;
        g_catF1[b*1024 + 512 + d] = 0.f;
        g_catF2[b*1024 + d]       = 0.f;
        g_catF2[b*1024 + 512 + d] = 0.f;
        g_hcat[b*1024 + d]        = 0.f;
        g_hcat[b*1024 + 512 + d]  = 0.f;
        g_ca[b*Hh + d] = 0.f;
        g_cf[b*Hh + d] = 0.f;
    }
}

// attention logits, fused q-partial reduction. grid (Bb, 7), 256 threads.
// b_alpha omitted: constant shift cancels in softmax.
__global__ void k_attlogits(const float* __restrict__ W_alpha) {
    int b = blockIdx.x;
    int c = blockIdx.y;        // 0..6, each handles 28 a's
    __shared__ float q[Ee];
    __shared__ float wa_s[Ee];
    int tid = threadIdx.x;
    for (int e = tid; e < Ee; e += 256) {
        float s = g_bq[e];
#pragma unroll
        for (int p = 0; p < 8; p++) s += g_qp[p][b*Ee + e];
        q[e] = s;
        wa_s[e] = W_alpha[e];
    }
    __syncthreads();
    int wid = tid >> 5, lane = tid & 31;
    for (int al = wid; al < 28; al += 8) {
        int a = c*28 + al;
        const float* pa = g_patt + ((size_t)(b*ATT) + a)*Ee;
        float acc = 0.f;
#pragma unroll
        for (int k = 0; k < 16; k++) {
            int e = lane + 32*k;
            acc += wa_s[e] * tanh_approx(q[e] + pa[e]);
        }
#pragma unroll
        for (int o = 16; o > 0; o >>= 1) acc += __shfl_down_sync(0xffffffffu, acc, o);
        if (lane == 0) g_attlog[b*ATT + a] = acc;
    }
}

// fused: softmax + (w @ P) in smem, cell for step i, gather for step i+1.
// grid Bb, 256 threads; per-batch dependency chain is block-local.
__global__ void k_wsumcell(int i, const int* __restrict__ word_idx, const int* __restrict__ father_idx,
                           const float* __restrict__ embed_tab,
                           const float* __restrict__ bias_H, const float* __restrict__ bias_I,
                           const float* __restrict__ bias_f1, const float* __restrict__ bias_f2) {
    int b = blockIdx.x;
    int tid = threadIdx.x;              // 256
    __shared__ float w[256];
    __shared__ float red[8];
    __shared__ float sv;
    __shared__ float cg_s[Hh];
    int wid = tid >> 5, lane = tid & 31;

    if (i > 0) {
        float v = (tid < ATT) ? g_attlog[b*ATT + tid] : -1e30f;
        float m = v;
#pragma unroll
        for (int o = 16; o > 0; o >>= 1) m = fmaxf(m, __shfl_xor_sync(0xffffffffu, m, o));
        if (lane == 0) red[wid] = m;
        __syncthreads();
        if (tid == 0) {
            float mm = red[0];
            for (int k = 1; k < 8; k++) mm = fmaxf(mm, red[k]);
            sv = mm;
        }
        __syncthreads();
        float e = (tid < ATT) ? __expf(v - sv) : 0.f;
        float s = e;
#pragma unroll
        for (int o = 16; o > 0; o >>= 1) s += __shfl_xor_sync(0xffffffffu, s, o);
        __syncthreads();
        if (lane == 0) red[wid] = s;
        __syncthreads();
        if (tid == 0) {
            float ss = 0.f;
            for (int k = 0; k < 8; k++) ss += red[k];
            sv = ss;
        }
        __syncthreads();
        w[tid] = e / sv;
        __syncthreads();

        int d0 = tid * 2;   // 0..510
        const float* base = g_pI + (size_t)b*ATT*Hh + d0;
        float ax = 0.f, ay = 0.f;
#pragma unroll 4
        for (int a = 0; a < ATT; a++) {
            float2 v2 = *(const float2*)&base[(size_t)a*Hh];
            float ww = w[a];
            ax += ww * v2.x; ay += ww * v2.y;
        }
        cg_s[d0] = ax; cg_s[d0 + 1] = ay;
    } else {
        for (int d = tid; d < Hh; d += 256) cg_s[d] = g_cgatt[b*Hh + d];
    }
    __syncthreads();

    // ---- cell for step i ----
    for (int d = tid; d < Hh; d += 256) {
        float gi = bias_H[d], go = bias_H[Hh + d];
#pragma unroll
        for (int p = 0; p < 16; p++) { gi += g_gatesP[p][b*1024 + d]; go += g_gatesP[p][b*1024 + 512 + d]; }
        float cg = bias_I[d] + cg_s[d];
#pragma unroll
        for (int p = 0; p < 16; p++) cg += g_cg0P[p][b*Hh + d];
        float f1 = bias_f1[d], f2 = bias_f2[d];
#pragma unroll
        for (int p = 0; p < 8; p++) { f1 += g_f1P[p][b*Hh + d]; f2 += g_f2P[p][b*Hh + d]; }
        gi = 1.f/(1.f + expf(-gi));
        go = 1.f/(1.f + expf(-go));
        cg = tanhf(cg);
        f1 = 1.f/(1.f + expf(-f1));
        f2 = 1.f/(1.f + expf(-f2));
        float nc = f1*g_ca[b*Hh + d] + f2*g_cf[b*Hh + d] + gi*cg;
        float nh = go * tanhf(nc);
        g_h[(b*Tt + i)*Hh + d] = nh;
        g_c[(b*Tt + i)*Hh + d] = nc;
    }
    __syncthreads();   // block-scope fence: h/c writes visible below

    // ---- gather for step i+1 ----
    int ni = i + 1;
    if (ni >= Tt) return;
    int father = father_idx[b*Tt + ni];
    bool useF = (((ni - 1) % 3) != 0);
    int wa = word_idx[b*Tt + father];
    int wf = word_idx[b*Tt + ni - 1];
    for (int d = tid; d < Hh; d += 256) {
        float xa = embed_tab[(size_t)wa*Ee + d];
        float ha = g_h[(b*Tt + father)*Hh + d];
        float ca = g_c[(b*Tt + father)*Hh + d];
        float xf = 0.f, hf = 0.f, cf = 0.f;
        if (useF) {
            xf = embed_tab[(size_t)wf*Ee + d];
            hf = g_h[(b*Tt + ni - 1)*Hh + d];
            cf = g_c[(b*Tt + ni - 1)*Hh + d];
        }
        g_catX[b*2048 + d]        = xa;
        g_catX[b*2048 + 512 + d]  = xf;
        g_catX[b*2048 + 1024 + d] = ha;
        g_catX[b*2048 + 1536 + d] = hf;
        g_catF1[b*1024 + d]       = xa;
        g_catF1[b*1024 + 512 + d] = ha;
        g_catF2[b*1024 + d]       = xf;
        g_catF2[b*1024 + 512 + d] = hf;
        g_hcat[b*1024 + d]        = ha;
        g_hcat[b*1024 + 512 + d]  = hf;
        g_ca[b*Hh + d] = ca;
        g_cf[b*Hh + d] = cf;
    }
}

// 1-pass online log-softmax over V=10000
__global__ void k_logsoftmax(float* __restrict__ out) {
    int r = blockIdx.x;                 // B*T rows
    float* row = out + (size_t)r*Vv;
    int tid = threadIdx.x;              // 256
    int wid = tid >> 5, lane = tid & 31;
    __shared__ float rm[8], rs[8];
    __shared__ float svM, svS;

    float m = -1e30f, s = 0.f;
    for (int j = tid; j < Vv; j += 256) {
        float v = row[j];
        if (v > m) { s = s*__expf(m - v) + 1.f; m = v; }
        else s += __expf(v - m);
    }
#pragma unroll
    for (int o = 16; o > 0; o >>= 1) {
        float mo = __shfl_xor_sync(0xffffffffu, m, o);
        float so = __shfl_xor_sync(0xffffffffu, s, o);
        float M = fmaxf(m, mo);
        s = s*__expf(m - M) + so*__expf(mo - M);
        m = M;
    }
    if (lane == 0) { rm[wid] = m; rs[wid] = s; }
    __syncthreads();
    if (tid == 0) {
        float M = rm[0], S = rs[0];
        for (int k = 1; k < 8; k++) {
            float M2 = fmaxf(M, rm[k]);
            S = S*__expf(M - M2) + rs[k]*__expf(rm[k] - M2);
            M = M2;
        }
        svM = M; svS = S;
    }
    __syncthreads();
    float lse = svM + logf(svS);
    for (int j = tid; j < Vv; j += 256) row[j] -= lse;
}

// ---------------- host ----------------
extern "C" void kernel_launch(void* const* d_in, const int* in_sizes, int n_in,
                              void* d_out, int out_size) {
    const int*   word_idx   = (const int*)d_in[0];
    const int*   father_idx = (const int*)d_in[1];
    const float* fc_feats   = (const float*)d_in[2];
    const float* att_feats  = (const float*)d_in[3];
    const float* W_fc       = (const float*)d_in[4];
    const float* b_fc       = (const float*)d_in[5];
    const float* W_att      = (const float*)d_in[6];
    const float* b_att      = (const float*)d_in[7];
    const float* embed_tab  = (const float*)d_in[8];
    const float* weight_f1  = (const float*)d_in[9];
    const float* bias_f1    = (const float*)d_in[10];
    const float* weight_f2  = (const float*)d_in[11];
    const float* bias_f2    = (const float*)d_in[12];
    const float* weight_H   = (const float*)d_in[13];
    const float* bias_H     = (const float*)d_in[14];
    const float* weight_I   = (const float*)d_in[15];
    const float* bias_I     = (const float*)d_in[16];
    const float* W_ha       = (const float*)d_in[17];
    const float* b_ha       = (const float*)d_in[18];
    const float* W_hf       = (const float*)d_in[19];
    const float* b_hf       = (const float*)d_in[20];
    const float* W_alpha    = (const float*)d_in[21];
    const float* b_alpha    = (const float*)d_in[22];
    const float* W_logit    = (const float*)d_in[23];
    const float* b_logit    = (const float*)d_in[24];
    float* out = (float*)d_out;
    (void)b_alpha; (void)n_in; (void)in_sizes; (void)out_size;

    // ---- one-time preprocessing ----
    k_zero_hc<<<512, 256>>>();
    k_build_wq<<<Ee, 256>>>(W_ha, b_ha, W_hf, b_hf);
    // fc_emb partials
    k_gemm_small2<<<32, 256>>>(0, fc_feats, W_fc, weight_H, weight_I, weight_f1, weight_f2);
    // p_att = att_feats @ W_att^T + b_att
    {
        dim3 g(Ee/128, (Bb*ATT)/128);   // (4, 98)
        k_gemm_big<<<g, 256>>>(0, att_feats, W_att, AF, b_att, nullptr, Bb*ATT, Ee, AF);
    }
    // P = att_feats @ WI_att^T   (WI_att = weight_I columns [2048:4096])
    {
        dim3 g(Hh/128, (Bb*ATT)/128);   // (4, 98)
        k_gemm_big<<<g, 256>>>(2, att_feats, weight_I + 2048, 4096, nullptr, nullptr, Bb*ATT, Hh, AF);
    }
    // step-0 attention part: mean over P rows
    {
        dim3 g(Bb, 4);
        k_pmean<<<g, 128>>>();
    }
    k_gather0<<<Bb, 256>>>(b_fc);

    // ---- sequential tree-LSTM steps ----
    for (int i = 0; i < Tt; i++) {
        // combined gates/cg0/f1/f2/q GEMM (K-slice 128)
        k_gemm_small2<<<288, 256>>>(2, fc_feats, W_fc, weight_H, weight_I, weight_f1, weight_f2);
        if (i > 0) {
            dim3 ga(Bb, 7);
            k_attlogits<<<ga, 256>>>(W_alpha);
        }
        k_wsumcell<<<Bb, 256>>>(i, word_idx, father_idx, embed_tab,
                                bias_H, bias_I, bias_f1, bias_f2);
    }

    // logits = h_flat @ W_logit^T + b_logit -> out, then log_softmax in-place
    {
        dim3 g((Vv + 127)/128, (Bb*Tt)/128);  // (79, 24)
        k_gemm_big<<<g, 256>>>(1, nullptr, W_logit, Hh, b_logit, out, Bb*Tt, Vv, Hh);
    }
    k_logsoftmax<<<Bb*Tt, 256>>>(out);
}

// round 16
// speedup vs baseline: 5.1789x; 1.7298x over previous
#include <cuda_runtime.h>
#include <cuda_bf16.h>
#include <math.h>
#include <stdint.h>

#define Bb  64
#define Tt  48
#define Hh  512
#define Ee  512
#define ATT 196
#define AF  2048
#define FCD 2048
#define Vv  10000
#define VPAD 10112

// ---------------- device scratch (no allocs allowed) ----------------
__device__ __align__(16) float g_h[Bb*Tt*Hh];
__device__ __align__(16) float g_c[Bb*Tt*Hh];
__device__ __align__(16) float g_fcp[8][Bb*Ee];
__device__ __align__(16) float g_patt[Bb*ATT*Ee];     // att_feats @ W_att^T + b_att
__device__ __align__(16) float g_pI[Bb*ATT*Hh];       // att_feats @ WI_att^T
__device__ __align__(16) float g_Wq[Ee*1024];
__device__ __align__(16) float g_bq[Ee];
__device__ __align__(16) float g_catX[Bb*2048];       // [x1,x2,h1,h2]
__device__ __align__(16) float g_catF1[Bb*1024];
__device__ __align__(16) float g_catF2[Bb*1024];
__device__ __align__(16) float g_hcat[Bb*1024];
__device__ __align__(16) float g_qp[8][Bb*Hh];
__device__ __align__(16) float g_attlog[Bb*ATT];
__device__ __align__(16) float g_gatesP[16][Bb*1024];
__device__ __align__(16) float g_cg0P[16][Bb*Hh];
__device__ __align__(16) float g_cgatt[Bb*Hh];
__device__ __align__(16) float g_f1P[8][Bb*Hh];
__device__ __align__(16) float g_f2P[8][Bb*Hh];
__device__ __align__(16) float g_ca[Bb*Hh];
__device__ __align__(16) float g_cf[Bb*Hh];

// ---- packed bf16 hi/lo (u32 = 2 bf16, k-pairs) converted once at init ----
__device__ __align__(16) unsigned cAFH[Bb*ATT*1024], cAFL[Bb*ATT*1024];     // att_feats [12544][1024]
__device__ __align__(16) unsigned cWATH[Ee*1024],  cWATL[Ee*1024];          // W_att
__device__ __align__(16) unsigned cWIATH[Hh*1024], cWIATL[Hh*1024];         // weight_I cols[2048:4096]
__device__ __align__(16) unsigned cWLH[VPAD*256],  cWLL[VPAD*256];          // W_logit (padded rows)
__device__ __align__(16) unsigned cWHH[1024*1024], cWHL[1024*1024];         // weight_H
__device__ __align__(16) unsigned cWIH[Hh*1024],   cWIL[Hh*1024];           // weight_I cols[0:2048]
__device__ __align__(16) unsigned cWF1H[Hh*512],   cWF1L[Hh*512];
__device__ __align__(16) unsigned cWF2H[Hh*512],   cWF2L[Hh*512];
__device__ __align__(16) unsigned cWQH[Hh*512],    cWQL[Hh*512];

__device__ __forceinline__ float tanh_approx(float x) {
    float y;
    asm("tanh.approx.f32 %0, %1;" : "=f"(y) : "f"(x));
    return y;
}

__device__ __forceinline__ void cvt2(float f0, float f1, unsigned &h, unsigned &l) {
    __nv_bfloat162 hb = __floats2bfloat162_rn(f0, f1);
    float g0 = __bfloat162float(hb.x), g1 = __bfloat162float(hb.y);
    __nv_bfloat162 lb = __floats2bfloat162_rn(f0 - g0, f1 - g1);
    h = *reinterpret_cast<unsigned*>(&hb);
    l = *reinterpret_cast<unsigned*>(&lb);
}

__device__ __forceinline__ void mma_bf16(float* d, const unsigned* a, unsigned b0, unsigned b1) {
    asm volatile("mma.sync.aligned.m16n8k16.row.col.f32.bf16.bf16.f32 "
        "{%0,%1,%2,%3}, {%4,%5,%6,%7}, {%8,%9}, {%0,%1,%2,%3};"
        : "+f"(d[0]), "+f"(d[1]), "+f"(d[2]), "+f"(d[3])
        : "r"(a[0]), "r"(a[1]), "r"(a[2]), "r"(a[3]), "r"(b0), "r"(b1));
}

// ---------------- init kernels ----------------
__global__ void k_zero_hc() {
    int idx = blockIdx.x * blockDim.x + threadIdx.x;
    int n = Bb*Tt*Hh;
    for (int i = idx; i < n; i += gridDim.x * blockDim.x) { g_h[i] = 0.f; g_c[i] = 0.f; }
}

__global__ void k_build_wq(const float* __restrict__ W_ha, const float* __restrict__ b_ha,
                           const float* __restrict__ W_hf, const float* __restrict__ b_hf) {
    int n = blockIdx.x;
    for (int k = threadIdx.x; k < Hh; k += blockDim.x) {
        g_Wq[n*1024 + k]      = W_ha[n*Hh + k];
        g_Wq[n*1024 + Hh + k] = W_hf[n*Hh + k];
    }
    if (threadIdx.x == 0) g_bq[n] = b_ha[n] + b_hf[n];
}

// convert fp32 [R rows, C cols, row stride ld] -> packed hi/lo u32 [Rpad][C/2]
__global__ void k_cvt(int which, const float* __restrict__ src, int ld, int R, int C, int Rpad) {
    unsigned *dH, *dL;
    switch (which) {
        case 0: dH = cAFH;  dL = cAFL;  break;
        case 1: dH = cWATH; dL = cWATL; break;
        case 2: dH = cWIATH;dL = cWIATL;break;
        case 3: dH = cWLH;  dL = cWLL;  break;
        case 4: dH = cWHH;  dL = cWHL;  break;
        case 5: dH = cWIH;  dL = cWIL;  break;
        case 6: dH = cWF1H; dL = cWF1L; break;
        case 7: dH = cWF2H; dL = cWF2L; break;
        default: dH = cWQH; dL = cWQL; src = g_Wq; break;
    }
    int C2 = C >> 1;
    long total = (long)Rpad * C2;
    long stride = (long)gridDim.x * blockDim.x;
    for (long idx = (long)blockIdx.x*blockDim.x + threadIdx.x; idx < total; idx += stride) {
        int r = (int)(idx / C2), cp = (int)(idx % C2);
        float f0 = 0.f, f1 = 0.f;
        if (r < R) {
            const float* p = src + (size_t)r*ld + 2*cp;
            f0 = p[0]; f1 = p[1];
        }
        unsigned h, l;
        cvt2(f0, f1, h, l);
        dH[idx] = h; dL[idx] = l;
    }
}

// mean over ATT of P rows -> g_cgatt
__global__ void k_pmean() {
    int b = blockIdx.x;
    int d = blockIdx.y * 128 + threadIdx.x;
    const float* p = g_pI + ((size_t)b*ATT)*Hh + d;
    float acc = 0.f;
#pragma unroll 4
    for (int a = 0; a < ATT; a++) acc += p[(size_t)a*Hh];
    g_cgatt[b*Hh + d] = acc * (1.0f/ATT);
}

// ---------------- big GEMM (bf16x3 tensor, precomputed operands) ----------------
// C[M,N] = A[M,K] @ W[N,K]^T (+ bias). 128x128 tile, Ktile 32, 8 warps (4m x 2n of 32x64).
// mode 0: A=cAF, W=cWAT, C=g_patt | mode 2: A=cAF, W=cWIAT, C=g_pI
// mode 1: A=g_h fp32 (convert in staging), W=cWL (row-padded), C=Cext
__global__ void __launch_bounds__(256, 2)
k_gemm_bigbf(int mode, const float* __restrict__ bias, float* __restrict__ Cext,
             int M, int N, int K) {
    const unsigned *AH = nullptr, *AL = nullptr, *WHp, *WLp;
    float* C;
    if (mode == 0)      { AH = cAFH; AL = cAFL; WHp = cWATH;  WLp = cWATL;  C = g_patt; }
    else if (mode == 2) { AH = cAFH; AL = cAFL; WHp = cWIATH; WLp = cWIATL; C = g_pI; }
    else                { WHp = cWLH; WLp = cWLL; C = Cext; }
    int K2 = K >> 1;

    __shared__ unsigned sAH[128][20], sAL[128][20], sWH[128][20], sWL[128][20];

    int tid = threadIdx.x;
    int m0 = blockIdx.y * 128, n0 = blockIdx.x * 128;
    int warp = tid >> 5, lane = tid & 31;
    int grp = lane >> 2, qd = lane & 3;
    int wm = (warp & 3) * 32;    // mi in {0,1} -> rows wm+mi*16
    int wn = (warp >> 2) * 64;   // ni in 0..7 -> cols wn+ni*8
    int sr = tid >> 1, sc = (tid & 1) * 8;

    float acc[2][8][4];
#pragma unroll
    for (int mi = 0; mi < 2; mi++)
#pragma unroll
        for (int ni = 0; ni < 8; ni++)
#pragma unroll
            for (int r = 0; r < 4; r++) acc[mi][ni][r] = 0.f;

    for (int k0 = 0; k0 < K2; k0 += 16) {
        uint4 va0, va1, vb0, vb1;
        unsigned hh[8], ll[8];
        if (mode != 1) {
            const unsigned* ah = &AH[(size_t)(m0 + sr)*K2 + k0 + sc];
            const unsigned* al = &AL[(size_t)(m0 + sr)*K2 + k0 + sc];
            va0 = *(const uint4*)ah;       va1 = *(const uint4*)(ah + 4);
            vb0 = *(const uint4*)al;       vb1 = *(const uint4*)(al + 4);
        } else {
            const float* ap = g_h + (size_t)(m0 + sr)*K + 2*(k0 + sc);
            float4 f0 = *(const float4*)ap;
            float4 f1 = *(const float4*)(ap + 4);
            float4 f2 = *(const float4*)(ap + 8);
            float4 f3 = *(const float4*)(ap + 12);
            cvt2(f0.x, f0.y, hh[0], ll[0]); cvt2(f0.z, f0.w, hh[1], ll[1]);
            cvt2(f1.x, f1.y, hh[2], ll[2]); cvt2(f1.z, f1.w, hh[3], ll[3]);
            cvt2(f2.x, f2.y, hh[4], ll[4]); cvt2(f2.z, f2.w, hh[5], ll[5]);
            cvt2(f3.x, f3.y, hh[6], ll[6]); cvt2(f3.z, f3.w, hh[7], ll[7]);
        }
        const unsigned* wh = &WHp[(size_t)(n0 + sr)*K2 + k0 + sc];
        const unsigned* wl = &WLp[(size_t)(n0 + sr)*K2 + k0 + sc];
        uint4 vw0 = *(const uint4*)wh, vw1 = *(const uint4*)(wh + 4);
        uint4 vx0 = *(const uint4*)wl, vx1 = *(const uint4*)(wl + 4);

        __syncthreads();
        if (mode != 1) {
            *(uint4*)&sAH[sr][sc]     = va0; *(uint4*)&sAH[sr][sc + 4] = va1;
            *(uint4*)&sAL[sr][sc]     = vb0; *(uint4*)&sAL[sr][sc + 4] = vb1;
        } else {
            *(uint4*)&sAH[sr][sc]     = make_uint4(hh[0], hh[1], hh[2], hh[3]);
            *(uint4*)&sAH[sr][sc + 4] = make_uint4(hh[4], hh[5], hh[6], hh[7]);
            *(uint4*)&sAL[sr][sc]     = make_uint4(ll[0], ll[1], ll[2], ll[3]);
            *(uint4*)&sAL[sr][sc + 4] = make_uint4(ll[4], ll[5], ll[6], ll[7]);
        }
        *(uint4*)&sWH[sr][sc]     = vw0; *(uint4*)&sWH[sr][sc + 4] = vw1;
        *(uint4*)&sWL[sr][sc]     = vx0; *(uint4*)&sWL[sr][sc + 4] = vx1;
        __syncthreads();

#pragma unroll
        for (int ks = 0; ks < 2; ks++) {
            int kc = ks * 8;
            unsigned aH[2][4], aL[2][4];
#pragma unroll
            for (int mi = 0; mi < 2; mi++) {
                int r = wm + mi*16 + grp;
                aH[mi][0] = sAH[r][kc + qd];     aH[mi][1] = sAH[r + 8][kc + qd];
                aH[mi][2] = sAH[r][kc + qd + 4]; aH[mi][3] = sAH[r + 8][kc + qd + 4];
                aL[mi][0] = sAL[r][kc + qd];     aL[mi][1] = sAL[r + 8][kc + qd];
                aL[mi][2] = sAL[r][kc + qd + 4]; aL[mi][3] = sAL[r + 8][kc + qd + 4];
            }
#pragma unroll
            for (int ni = 0; ni < 8; ni++) {
                int cn = wn + ni*8 + grp;
                unsigned bh0 = sWH[cn][kc + qd], bh1 = sWH[cn][kc + qd + 4];
                unsigned bl0 = sWL[cn][kc + qd], bl1 = sWL[cn][kc + qd + 4];
#pragma unroll
                for (int mi = 0; mi < 2; mi++) {
                    mma_bf16(acc[mi][ni], aH[mi], bl0, bl1);
                    mma_bf16(acc[mi][ni], aL[mi], bh0, bh1);
                    mma_bf16(acc[mi][ni], aH[mi], bh0, bh1);
                }
            }
        }
    }

#pragma unroll
    for (int mi = 0; mi < 2; mi++)
#pragma unroll
        for (int ni = 0; ni < 8; ni++) {
            int r0 = m0 + wm + mi*16 + grp;
            int cb = n0 + wn + ni*8 + 2*qd;
            if (cb < N) {
                float bv0 = bias ? bias[cb] : 0.f;
                float bv1 = bias ? bias[cb + 1] : 0.f;
                float* d = acc[mi][ni];
                *(float2*)&C[(size_t)r0*N + cb]       = make_float2(d[0] + bv0, d[1] + bv1);
                *(float2*)&C[(size_t)(r0 + 8)*N + cb] = make_float2(d[2] + bv0, d[3] + bv1);
            }
        }
}

// ---------------- per-step multi-job GEMM (bf16x3 tensor) ----------------
// M=64, tile 64x128, Ktile 32, K-slice 256. 144 blocks: gates 64, cg0 32, f1 16, f2 16, q 16.
// 8 warps = 2m x 4n of 32x32 warp tiles.
__global__ void __launch_bounds__(256)
k_gemm_step() {
    int bx = blockIdx.x;
    const float* A; int lda; const unsigned *WHp, *WLp; int ldw2; float* Cp; int N, ntile, local;
    if (bx < 64)       { A = g_catX;  lda = 2048; WHp = cWHH;  WLp = cWHL;  ldw2 = 1024; N = 1024; ntile = 8; Cp = &g_gatesP[0][0]; local = bx; }
    else if (bx < 96)  { A = g_catX;  lda = 2048; WHp = cWIH;  WLp = cWIL;  ldw2 = 1024; N = 512;  ntile = 4; Cp = &g_cg0P[0][0];   local = bx - 64; }
    else if (bx < 112) { A = g_catF1; lda = 1024; WHp = cWF1H; WLp = cWF1L; ldw2 = 512;  N = 512;  ntile = 4; Cp = &g_f1P[0][0];    local = bx - 96; }
    else if (bx < 128) { A = g_catF2; lda = 1024; WHp = cWF2H; WLp = cWF2L; ldw2 = 512;  N = 512;  ntile = 4; Cp = &g_f2P[0][0];    local = bx - 112; }
    else               { A = g_hcat;  lda = 1024; WHp = cWQH;  WLp = cWQL;  ldw2 = 512;  N = 512;  ntile = 4; Cp = &g_qp[0][0];     local = bx - 128; }
    int tile = local % ntile, split = local / ntile;
    int n0 = tile * 128, k0f = split * 256;

    __shared__ unsigned sAH[64][20], sAL[64][20], sWH[128][20], sWL[128][20];

    int tid = threadIdx.x;
    int warp = tid >> 5, lane = tid & 31;
    int grp = lane >> 2, qd = lane & 3;
    int wm = (warp & 1) * 32;
    int wn = (warp >> 1) * 32;
    int ar = tid >> 2, af = (tid & 3) * 8;     // A: 64 rows x 32 floats
    int wr = tid >> 1, wc = (tid & 1) * 8;     // W: 128 rows x 16 u32

    float acc[2][4][4];
#pragma unroll
    for (int mi = 0; mi < 2; mi++)
#pragma unroll
        for (int ni = 0; ni < 4; ni++)
#pragma unroll
            for (int r = 0; r < 4; r++) acc[mi][ni][r] = 0.f;

    for (int it = 0; it < 8; it++) {
        int kf = k0f + it*32;
        int ku = kf >> 1;
        const float* ap = A + (size_t)ar*lda + kf + af;
        float4 f0 = *(const float4*)ap;
        float4 f1 = *(const float4*)(ap + 4);
        unsigned h0,l0,h1,l1,h2,l2,h3,l3;
        cvt2(f0.x, f0.y, h0, l0); cvt2(f0.z, f0.w, h1, l1);
        cvt2(f1.x, f1.y, h2, l2); cvt2(f1.z, f1.w, h3, l3);
        const unsigned* wh = &WHp[(size_t)(n0 + wr)*ldw2 + ku + wc];
        const unsigned* wl = &WLp[(size_t)(n0 + wr)*ldw2 + ku + wc];
        uint4 vw0 = *(const uint4*)wh, vw1 = *(const uint4*)(wh + 4);
        uint4 vx0 = *(const uint4*)wl, vx1 = *(const uint4*)(wl + 4);

        __syncthreads();
        *(uint4*)&sAH[ar][(tid & 3)*4] = make_uint4(h0, h1, h2, h3);
        *(uint4*)&sAL[ar][(tid & 3)*4] = make_uint4(l0, l1, l2, l3);
        *(uint4*)&sWH[wr][wc]     = vw0; *(uint4*)&sWH[wr][wc + 4] = vw1;
        *(uint4*)&sWL[wr][wc]     = vx0; *(uint4*)&sWL[wr][wc + 4] = vx1;
        __syncthreads();

#pragma unroll
        for (int ks = 0; ks < 2; ks++) {
            int kc = ks * 8;
            unsigned aH[2][4], aL[2][4];
#pragma unroll
            for (int mi = 0; mi < 2; mi++) {
                int r = wm + mi*16 + grp;
                aH[mi][0] = sAH[r][kc + qd];     aH[mi][1] = sAH[r + 8][kc + qd];
                aH[mi][2] = sAH[r][kc + qd + 4]; aH[mi][3] = sAH[r + 8][kc + qd + 4];
                aL[mi][0] = sAL[r][kc + qd];     aL[mi][1] = sAL[r + 8][kc + qd];
                aL[mi][2] = sAL[r][kc + qd + 4]; aL[mi][3] = sAL[r + 8][kc + qd + 4];
            }
#pragma unroll
            for (int ni = 0; ni < 4; ni++) {
                int cn = wn + ni*8 + grp;
                unsigned bh0 = sWH[cn][kc + qd], bh1 = sWH[cn][kc + qd + 4];
                unsigned bl0 = sWL[cn][kc + qd], bl1 = sWL[cn][kc + qd + 4];
#pragma unroll
                for (int mi = 0; mi < 2; mi++) {
                    mma_bf16(acc[mi][ni], aH[mi], bl0, bl1);
                    mma_bf16(acc[mi][ni], aL[mi], bh0, bh1);
                    mma_bf16(acc[mi][ni], aH[mi], bh0, bh1);
                }
            }
        }
    }

    float* Cb = Cp + (size_t)split * 64 * N;
#pragma unroll
    for (int mi = 0; mi < 2; mi++)
#pragma unroll
        for (int ni = 0; ni < 4; ni++) {
            int r0 = wm + mi*16 + grp;
            int cb = n0 + wn + ni*8 + 2*qd;
            float* d = acc[mi][ni];
            *(float2*)&Cb[(size_t)r0*N + cb]       = make_float2(d[0], d[1]);
            *(float2*)&Cb[(size_t)(r0 + 8)*N + cb] = make_float2(d[2], d[3]);
        }
}

// ---------------- fc_emb partials (init-only, fp32) ----------------
// M=64 tile 64x128, N=512 (4 tiles), K=2048 slice 256 (8 splits) -> 32 blocks
__global__ void __launch_bounds__(256)
k_gemm_fc(const float* __restrict__ A, const float* __restrict__ W) {
    int tile = blockIdx.x % 4, split = blockIdx.x / 4;
    int n0 = tile * 128, k0 = split * 256;
    __shared__ float As[16][64];
    __shared__ float Ws[16][132];
    int tid = threadIdx.x;
    int tx = tid & 15, ty = tid >> 4;
    int ar = tid >> 2, ak = (tid & 3) * 4;
    int wr = tid >> 1, wk = (tid & 1) * 8;
    const float* Ap = A + (size_t)ar*FCD + k0 + ak;
    const float* Wp = W + (size_t)(n0 + wr)*FCD + k0 + wk;
    float acc[4][8];
#pragma unroll
    for (int i = 0; i < 4; i++)
#pragma unroll
        for (int j = 0; j < 8; j++) acc[i][j] = 0.f;
    for (int kk = 0; kk < 256; kk += 16) {
        {
            float4 v = *(const float4*)&Ap[kk];
            As[ak+0][ar] = v.x; As[ak+1][ar] = v.y; As[ak+2][ar] = v.z; As[ak+3][ar] = v.w;
        }
        {
            float4 w0 = *(const float4*)&Wp[kk];
            float4 w1 = *(const float4*)&Wp[kk + 4];
            Ws[wk+0][wr] = w0.x; Ws[wk+1][wr] = w0.y; Ws[wk+2][wr] = w0.z; Ws[wk+3][wr] = w0.w;
            Ws[wk+4][wr] = w1.x; Ws[wk+5][wr] = w1.y; Ws[wk+6][wr] = w1.z; Ws[wk+7][wr] = w1.w;
        }
        __syncthreads();
#pragma unroll
        for (int k = 0; k < 16; k++) {
            float4 a  = *(const float4*)&As[k][ty*4];
            float4 w0 = *(const float4*)&Ws[k][tx*8];
            float4 w1 = *(const float4*)&Ws[k][tx*8 + 4];
            float av[4] = {a.x,a.y,a.z,a.w};
            float wv[8] = {w0.x,w0.y,w0.z,w0.w,w1.x,w1.y,w1.z,w1.w};
#pragma unroll
            for (int i = 0; i < 4; i++)
#pragma unroll
                for (int j = 0; j < 8; j++) acc[i][j] += av[i]*wv[j];
        }
        __syncthreads();
    }
    float* Cb = &g_fcp[0][0] + (size_t)split * 64 * Ee;
#pragma unroll
    for (int i = 0; i < 4; i++) {
        int m = ty*4 + i;
        *(float4*)&Cb[(size_t)m*Ee + n0 + tx*8]     = make_float4(acc[i][0],acc[i][1],acc[i][2],acc[i][3]);
        *(float4*)&Cb[(size_t)m*Ee + n0 + tx*8 + 4] = make_float4(acc[i][4],acc[i][5],acc[i][6],acc[i][7]);
    }
}

// ---------------- gather for step 0 only ----------------
__global__ void k_gather0(const float* __restrict__ b_fc) {
    int b = blockIdx.x;
    for (int d = threadIdx.x; d < Hh; d += blockDim.x) {
        float s = b_fc[d];
#pragma unroll
        for (int p = 0; p < 8; p++) s += g_fcp[p][b*Ee + d];
        float xa = s;
        g_catX[b*2048 + d]        = xa;
        g_catX[b*2048 + 512 + d]  = 0.f;
        g_catX[b*2048 + 1024 + d] = 0.f;
        g_catX[b*2048 + 1536 + d] = 0.f;
        g_catF1[b*1024 + d]       = xa;
        g_catF1[b*1024 + 512 + d] = 0.f;
        g_catF2[b*1024 + d]       = 0.f;
        g_catF2[b*1024 + 512 + d] = 0.f;
        g_hcat[b*1024 + d]        = 0.f;
        g_hcat[b*1024 + 512 + d]  = 0.f;
        g_ca[b*Hh + d] = 0.f;
        g_cf[b*Hh + d] = 0.f;
    }
}

// attention logits. grid (Bb, 7), 256 threads. q partials = 4 splits now.
__global__ void k_attlogits(const float* __restrict__ W_alpha) {
    int b = blockIdx.x;
    int c = blockIdx.y;
    __shared__ float q[Ee];
    __shared__ float wa_s[Ee];
    int tid = threadIdx.x;
    for (int e = tid; e < Ee; e += 256) {
        float s = g_bq[e];
#pragma unroll
        for (int p = 0; p < 4; p++) s += g_qp[p][b*Ee + e];
        q[e] = s;
        wa_s[e] = W_alpha[e];
    }
    __syncthreads();
    int wid = tid >> 5, lane = tid & 31;
    for (int al = wid; al < 28; al += 8) {
        int a = c*28 + al;
        const float* pa = g_patt + ((size_t)(b*ATT) + a)*Ee;
        float acc = 0.f;
#pragma unroll
        for (int k = 0; k < 16; k++) {
            int e = lane + 32*k;
            acc += wa_s[e] * tanh_approx(q[e] + pa[e]);
        }
#pragma unroll
        for (int o = 16; o > 0; o >>= 1) acc += __shfl_down_sync(0xffffffffu, acc, o);
        if (lane == 0) g_attlog[b*ATT + a] = acc;
    }
}

// fused: softmax + (w @ P) in smem, cell for step i, gather for step i+1.
__global__ void k_wsumcell(int i, const int* __restrict__ word_idx, const int* __restrict__ father_idx,
                           const float* __restrict__ embed_tab,
                           const float* __restrict__ bias_H, const float* __restrict__ bias_I,
                           const float* __restrict__ bias_f1, const float* __restrict__ bias_f2) {
    int b = blockIdx.x;
    int tid = threadIdx.x;              // 256
    __shared__ float w[256];
    __shared__ float red[8];
    __shared__ float sv;
    __shared__ float cg_s[Hh];
    int wid = tid >> 5, lane = tid & 31;

    if (i > 0) {
        float v = (tid < ATT) ? g_attlog[b*ATT + tid] : -1e30f;
        float m = v;
#pragma unroll
        for (int o = 16; o > 0; o >>= 1) m = fmaxf(m, __shfl_xor_sync(0xffffffffu, m, o));
        if (lane == 0) red[wid] = m;
        __syncthreads();
        if (tid == 0) {
            float mm = red[0];
            for (int k = 1; k < 8; k++) mm = fmaxf(mm, red[k]);
            sv = mm;
        }
        __syncthreads();
        float e = (tid < ATT) ? __expf(v - sv) : 0.f;
        float s = e;
#pragma unroll
        for (int o = 16; o > 0; o >>= 1) s += __shfl_xor_sync(0xffffffffu, s, o);
        __syncthreads();
        if (lane == 0) red[wid] = s;
        __syncthreads();
        if (tid == 0) {
            float ss = 0.f;
            for (int k = 0; k < 8; k++) ss += red[k];
            sv = ss;
        }
        __syncthreads();
        w[tid] = e / sv;
        __syncthreads();

        int d0 = tid * 2;
        const float* base = g_pI + (size_t)b*ATT*Hh + d0;
        float ax = 0.f, ay = 0.f;
#pragma unroll 4
        for (int a = 0; a < ATT; a++) {
            float2 v2 = *(const float2*)&base[(size_t)a*Hh];
            float ww = w[a];
            ax += ww * v2.x; ay += ww * v2.y;
        }
        cg_s[d0] = ax; cg_s[d0 + 1] = ay;
    } else {
        for (int d = tid; d < Hh; d += 256) cg_s[d] = g_cgatt[b*Hh + d];
    }
    __syncthreads();

    // ---- cell for step i (8/8/4/4 partials) ----
    for (int d = tid; d < Hh; d += 256) {
        float gi = bias_H[d], go = bias_H[Hh + d];
#pragma unroll
        for (int p = 0; p < 8; p++) { gi += g_gatesP[p][b*1024 + d]; go += g_gatesP[p][b*1024 + 512 + d]; }
        float cg = bias_I[d] + cg_s[d];
#pragma unroll
        for (int p = 0; p < 8; p++) cg += g_cg0P[p][b*Hh + d];
        float f1 = bias_f1[d], f2 = bias_f2[d];
#pragma unroll
        for (int p = 0; p < 4; p++) { f1 += g_f1P[p][b*Hh + d]; f2 += g_f2P[p][b*Hh + d]; }
        gi = 1.f/(1.f + expf(-gi));
        go = 1.f/(1.f + expf(-go));
        cg = tanhf(cg);
        f1 = 1.f/(1.f + expf(-f1));
        f2 = 1.f/(1.f + expf(-f2));
        float nc = f1*g_ca[b*Hh + d] + f2*g_cf[b*Hh + d] + gi*cg;
        float nh = go * tanhf(nc);
        g_h[(b*Tt + i)*Hh + d] = nh;
        g_c[(b*Tt + i)*Hh + d] = nc;
    }
    __syncthreads();

    // ---- gather for step i+1 ----
    int ni = i + 1;
    if (ni >= Tt) return;
    int father = father_idx[b*Tt + ni];
    bool useF = (((ni - 1) % 3) != 0);
    int wa = word_idx[b*Tt + father];
    int wf = word_idx[b*Tt + ni - 1];
    for (int d = tid; d < Hh; d += 256) {
        float xa = embed_tab[(size_t)wa*Ee + d];
        float ha = g_h[(b*Tt + father)*Hh + d];
        float ca = g_c[(b*Tt + father)*Hh + d];
        float xf = 0.f, hf = 0.f, cf = 0.f;
        if (useF) {
            xf = embed_tab[(size_t)wf*Ee + d];
            hf = g_h[(b*Tt + ni - 1)*Hh + d];
            cf = g_c[(b*Tt + ni - 1)*Hh + d];
        }
        g_catX[b*2048 + d]        = xa;
        g_catX[b*2048 + 512 + d]  = xf;
        g_catX[b*2048 + 1024 + d] = ha;
        g_catX[b*2048 + 1536 + d] = hf;
        g_catF1[b*1024 + d]       = xa;
        g_catF1[b*1024 + 512 + d] = ha;
        g_catF2[b*1024 + d]       = xf;
        g_catF2[b*1024 + 512 + d] = hf;
        g_hcat[b*1024 + d]        = ha;
        g_hcat[b*1024 + 512 + d]  = hf;
        g_ca[b*Hh + d] = ca;
        g_cf[b*Hh + d] = cf;
    }
}

// 1-pass online log-softmax
__global__ void k_logsoftmax(float* __restrict__ out) {
    int r = blockIdx.x;
    float* row = out + (size_t)r*Vv;
    int tid = threadIdx.x;
    int wid = tid >> 5, lane = tid & 31;
    __shared__ float rm[8], rs[8];
    __shared__ float svM, svS;

    float m = -1e30f, s = 0.f;
    for (int j = tid; j < Vv; j += 256) {
        float v = row[j];
        if (v > m) { s = s*__expf(m - v) + 1.f; m = v; }
        else s += __expf(v - m);
    }
#pragma unroll
    for (int o = 16; o > 0; o >>= 1) {
        float mo = __shfl_xor_sync(0xffffffffu, m, o);
        float so = __shfl_xor_sync(0xffffffffu, s, o);
        float M = fmaxf(m, mo);
        s = s*__expf(m - M) + so*__expf(mo - M);
        m = M;
    }
    if (lane == 0) { rm[wid] = m; rs[wid] = s; }
    __syncthreads();
    if (tid == 0) {
        float M = rm[0], S = rs[0];
        for (int k = 1; k < 8; k++) {
            float M2 = fmaxf(M, rm[k]);
            S = S*__expf(M - M2) + rs[k]*__expf(rm[k] - M2);
            M = M2;
        }
        svM = M; svS = S;
    }
    __syncthreads();
    float lse = svM + logf(svS);
    for (int j = tid; j < Vv; j += 256) row[j] -= lse;
}

// ---------------- host ----------------
extern "C" void kernel_launch(void* const* d_in, const int* in_sizes, int n_in,
                              void* d_out, int out_size) {
    const int*   word_idx   = (const int*)d_in[0];
    const int*   father_idx = (const int*)d_in[1];
    const float* fc_feats   = (const float*)d_in[2];
    const float* att_feats  = (const float*)d_in[3];
    const float* W_fc       = (const float*)d_in[4];
    const float* b_fc       = (const float*)d_in[5];
    const float* W_att      = (const float*)d_in[6];
    const float* b_att      = (const float*)d_in[7];
    const float* embed_tab  = (const float*)d_in[8];
    const float* weight_f1  = (const float*)d_in[9];
    const float* bias_f1    = (const float*)d_in[10];
    const float* weight_f2  = (const float*)d_in[11];
    const float* bias_f2    = (const float*)d_in[12];
    const float* weight_H   = (const float*)d_in[13];
    const float* bias_H     = (const float*)d_in[14];
    const float* weight_I   = (const float*)d_in[15];
    const float* bias_I     = (const float*)d_in[16];
    const float* W_ha       = (const float*)d_in[17];
    const float* b_ha       = (const float*)d_in[18];
    const float* W_hf       = (const float*)d_in[19];
    const float* b_hf       = (const float*)d_in[20];
    const float* W_alpha    = (const float*)d_in[21];
    const float* b_alpha    = (const float*)d_in[22];
    const float* W_logit    = (const float*)d_in[23];
    const float* b_logit    = (const float*)d_in[24];
    float* out = (float*)d_out;
    (void)b_alpha; (void)n_in; (void)in_sizes; (void)out_size;

    // ---- one-time preprocessing ----
    k_zero_hc<<<512, 256>>>();
    k_build_wq<<<Ee, 256>>>(W_ha, b_ha, W_hf, b_hf);

    // bf16 hi/lo conversions (once per run)
    k_cvt<<<4096, 256>>>(0, att_feats, AF, Bb*ATT, AF, Bb*ATT);
    k_cvt<<<512, 256>>>(1, W_att, AF, Ee, AF, Ee);
    k_cvt<<<512, 256>>>(2, weight_I + 2048, 4096, Hh, 2048, Hh);
    k_cvt<<<1024, 256>>>(3, W_logit, Hh, Vv, Hh, VPAD);
    k_cvt<<<512, 256>>>(4, weight_H, 2048, 1024, 2048, 1024);
    k_cvt<<<512, 256>>>(5, weight_I, 4096, Hh, 2048, Hh);
    k_cvt<<<256, 256>>>(6, weight_f1, 1024, Hh, 1024, Hh);
    k_cvt<<<256, 256>>>(7, weight_f2, 1024, Hh, 1024, Hh);
    k_cvt<<<256, 256>>>(8, nullptr, 1024, Hh, 1024, Hh);

    // fc_emb partials (fp32)
    k_gemm_fc<<<32, 256>>>(fc_feats, W_fc);

    // p_att = att_feats @ W_att^T + b_att
    {
        dim3 g(Ee/128, (Bb*ATT)/128);   // (4, 98)
        k_gemm_bigbf<<<g, 256>>>(0, b_att, nullptr, Bb*ATT, Ee, AF);
    }
    // P = att_feats @ WI_att^T
    {
        dim3 g(Hh/128, (Bb*ATT)/128);   // (4, 98)
        k_gemm_bigbf<<<g, 256>>>(2, nullptr, nullptr, Bb*ATT, Hh, AF);
    }
    {
        dim3 g(Bb, 4);
        k_pmean<<<g, 128>>>();
    }
    k_gather0<<<Bb, 256>>>(b_fc);

    // ---- sequential tree-LSTM steps ----
    for (int i = 0; i < Tt; i++) {
        k_gemm_step<<<144, 256>>>();
        if (i > 0) {
            dim3 ga(Bb, 7);
            k_attlogits<<<ga, 256>>>(W_alpha);
        }
        k_wsumcell<<<Bb, 256>>>(i, word_idx, father_idx, embed_tab,
                                bias_H, bias_I, bias_f1, bias_f2);
    }

    // logits + log_softmax
    {
        dim3 g((Vv + 127)/128, (Bb*Tt)/128);  // (79, 24)
        k_gemm_bigbf<<<g, 256>>>(1, b_logit, out, Bb*Tt, Vv, Hh);
    }
    k_logsoftmax<<<Bb*Tt, 256>>>(out);
}